// round 2
// baseline (speedup 1.0000x reference)
#include <cuda_runtime.h>
#include <math.h>
#include <stdint.h>

// ---------------------------------------------------------------------------
// Problem constants (match reference)
// ---------------------------------------------------------------------------
#define BB    2
#define TSEQ  2048
#define DD    1024
#define HH    8
#define KDIM  128
#define VDIM  256
#define KEYD  1024          // H*KDIM
#define VALD  2048          // H*VDIM
#define NTOK  (BB*TSEQ)     // 4096
#define KS    4

// ---------------------------------------------------------------------------
// Scratch (device globals — no allocation allowed).
// Reuse plan:
//   g_qproj [16MB] : q pre-conv   -> later first half of ynorm
//   g_kproj [16MB] : k pre-conv   -> later second half of ynorm (contiguous w/ qproj NOT guaranteed -> use dedicated union block instead)
// To keep aliasing safe and simple, use one flat arena with explicit offsets.
// Layout (floats):
//   [0,          16M)  qproj   / later: ynorm (32MB needs 8M floats*4B... see below)
// Sizes in floats:
//   qproj: NTOK*KEYD = 4M floats
//   kproj: 4M
//   vproj: NTOK*VALD = 8M   -> reused as opre (8M) after conv_v
//   gproj: 8M               (live until normgate)
//   qc:    4M
//   kc:    4M
//   vc:    8M
//   alpha: 32K, beta: 32K
//   ynorm: 8M               -> reuse qproj(4M)+kproj(4M) region (contiguous in arena)
// Arena total: 4+4+8+8+4+4+8 M + eps = 40M floats = 160MB
// ---------------------------------------------------------------------------
#define OFF_QPROJ  (size_t)0                    // 4M floats
#define OFF_KPROJ  (OFF_QPROJ + (size_t)NTOK*KEYD)   // +4M
#define OFF_VPROJ  (OFF_KPROJ + (size_t)NTOK*KEYD)   // +8M
#define OFF_GPROJ  (OFF_VPROJ + (size_t)NTOK*VALD)   // +8M
#define OFF_QC     (OFF_GPROJ + (size_t)NTOK*VALD)   // +4M
#define OFF_KC     (OFF_QC    + (size_t)NTOK*KEYD)   // +4M
#define OFF_VC     (OFF_KC    + (size_t)NTOK*KEYD)   // +8M
#define OFF_AL     (OFF_VC    + (size_t)NTOK*VALD)
#define OFF_BE     (OFF_AL    + (size_t)NTOK*HH)
#define ARENA_F    (OFF_BE    + (size_t)NTOK*HH)
// aliases
#define OFF_OPRE   OFF_VPROJ    // vproj dead after conv_v
#define OFF_YNORM  OFF_QPROJ    // qproj+kproj dead after conv_q/k (8M contiguous)

__device__ float g_arena[ARENA_F];

// ---------------------------------------------------------------------------
// Generic fp32 SGEMM: C[M,N] = A[M,K] @ B[K,N]; all row-major.
// 128x128 block tile, BK=16, 8x8 per-thread micro-tile, 256 threads.
// Assumes M,N,K multiples of 128 (true for all uses here).
// ---------------------------------------------------------------------------
__global__ void __launch_bounds__(256) sgemm_kernel(
    const float* __restrict__ A, const float* __restrict__ B,
    float* __restrict__ C, int M, int N, int K)
{
    const int BM = 128, BN = 128, BK = 16;
    __shared__ float As[BK][BM];      // A stored transposed: As[k][m]
    __shared__ float Bs[BK][BN];

    int tid = threadIdx.x;
    int bm  = blockIdx.y, bn = blockIdx.x;

    int trow = (tid / 16) * 8;        // 0..120
    int tcol = (tid % 16) * 8;

    int arow = tid >> 1;              // 0..127
    int acol = (tid & 1) * 8;         // 0 or 8
    int brow = tid >> 4;              // 0..15
    int bcol = (tid & 15) * 8;

    const float* Ag = A + (size_t)(bm * BM + arow) * K + acol;
    const float* Bg = B + (size_t)brow * N + bn * BN + bcol;

    float acc[8][8];
#pragma unroll
    for (int i = 0; i < 8; i++)
#pragma unroll
        for (int j = 0; j < 8; j++) acc[i][j] = 0.f;

    for (int k0 = 0; k0 < K; k0 += BK) {
        float4 a0 = *(const float4*)(Ag + k0);
        float4 a1 = *(const float4*)(Ag + k0 + 4);
        float4 b0 = *(const float4*)(Bg + (size_t)k0 * N);
        float4 b1 = *(const float4*)(Bg + (size_t)k0 * N + 4);

        __syncthreads();
        As[acol + 0][arow] = a0.x;  As[acol + 1][arow] = a0.y;
        As[acol + 2][arow] = a0.z;  As[acol + 3][arow] = a0.w;
        As[acol + 4][arow] = a1.x;  As[acol + 5][arow] = a1.y;
        As[acol + 6][arow] = a1.z;  As[acol + 7][arow] = a1.w;
        *(float4*)&Bs[brow][bcol]     = b0;
        *(float4*)&Bs[brow][bcol + 4] = b1;
        __syncthreads();

#pragma unroll
        for (int kk = 0; kk < BK; kk++) {
            float af[8], bf[8];
            *(float4*)(af)     = *(const float4*)&As[kk][trow];
            *(float4*)(af + 4) = *(const float4*)&As[kk][trow + 4];
            *(float4*)(bf)     = *(const float4*)&Bs[kk][tcol];
            *(float4*)(bf + 4) = *(const float4*)&Bs[kk][tcol + 4];
#pragma unroll
            for (int i = 0; i < 8; i++)
#pragma unroll
                for (int j = 0; j < 8; j++)
                    acc[i][j] = fmaf(af[i], bf[j], acc[i][j]);
        }
    }

    float* Cp = C + (size_t)(bm * BM + trow) * N + bn * BN + tcol;
#pragma unroll
    for (int i = 0; i < 8; i++) {
        *(float4*)(Cp + (size_t)i * N)     = *(float4*)&acc[i][0];
        *(float4*)(Cp + (size_t)i * N + 4) = *(float4*)&acc[i][4];
    }
}

// ---------------------------------------------------------------------------
// a/b projections (N=8 each) + alpha/beta transforms, one token per block
// ---------------------------------------------------------------------------
__global__ void __launch_bounds__(256) ab_kernel(
    const float* __restrict__ x, const float* __restrict__ Wa,
    const float* __restrict__ Wb, const float* __restrict__ A_log,
    const float* __restrict__ dt_bias,
    float* __restrict__ alpha, float* __restrict__ beta)
{
    __shared__ float xs[DD];
    int t = blockIdx.x;
    for (int i = threadIdx.x; i < DD; i += 256)
        xs[i] = x[(size_t)t * DD + i];
    __syncthreads();

    int warp = threadIdx.x >> 5;     // 0..7 == head
    int lane = threadIdx.x & 31;

    float sa = 0.f, sb = 0.f;
    for (int kk = lane; kk < DD; kk += 32) {
        float xv = xs[kk];
        sa = fmaf(xv, Wa[kk * HH + warp], sa);
        sb = fmaf(xv, Wb[kk * HH + warp], sb);
    }
#pragma unroll
    for (int off = 16; off > 0; off >>= 1) {
        sa += __shfl_xor_sync(0xffffffffu, sa, off);
        sb += __shfl_xor_sync(0xffffffffu, sb, off);
    }
    if (lane == 0) {
        float z  = sa + dt_bias[warp];
        float sp = (z > 20.f) ? z : log1pf(expf(z));
        alpha[t * HH + warp] = expf(-expf(A_log[warp]) * sp);
        beta [t * HH + warp] = 2.f / (1.f + expf(-sb));
    }
}

// ---------------------------------------------------------------------------
// Fused depthwise causal conv (KS=4) + SiLU + l2norm for q/k.
// One warp per (token, head): lane owns 4 channels (float4).
// ---------------------------------------------------------------------------
__global__ void __launch_bounds__(256) conv_silu_l2_kernel(
    const float* __restrict__ in,   // [NTOK, KEYD] pre-conv
    const float* __restrict__ w,    // [KEYD, KS]
    float* __restrict__ out)        // [NTOK, KEYD] normalized
{
    int gw   = (blockIdx.x * 256 + threadIdx.x) >> 5;  // 0 .. NTOK*HH-1
    int lane = threadIdx.x & 31;
    int h    = gw % HH;
    int bt   = gw / HH;
    int t    = bt % TSEQ;
    int b    = bt / TSEQ;

    int cbase = h * KDIM + lane * 4;

    float acc[4] = {0.f, 0.f, 0.f, 0.f};
    float wt[4][KS];
#pragma unroll
    for (int c = 0; c < 4; c++)
#pragma unroll
        for (int j = 0; j < KS; j++)
            wt[c][j] = w[(cbase + c) * KS + j];

#pragma unroll
    for (int j = 0; j < KS; j++) {
        int tt = t + j - (KS - 1);
        if (tt >= 0) {
            float4 xv = *(const float4*)(in + ((size_t)(b * TSEQ + tt)) * KEYD + cbase);
#pragma unroll
            for (int c = 0; c < 4; c++) {
                float x = (&xv.x)[c];
                acc[c] = fmaf(wt[c][j], x, acc[c]);
            }
        }
    }

    float ss = 0.f;
#pragma unroll
    for (int c = 0; c < 4; c++) {
        acc[c] = acc[c] / (1.f + expf(-acc[c]));   // SiLU
        ss = fmaf(acc[c], acc[c], ss);
    }
#pragma unroll
    for (int off = 16; off > 0; off >>= 1)
        ss += __shfl_xor_sync(0xffffffffu, ss, off);
    float s = 1.f / fmaxf(sqrtf(ss), 1e-6f);

    float4 o;
#pragma unroll
    for (int c = 0; c < 4; c++) (&o.x)[c] = acc[c] * s;
    *(float4*)(out + (size_t)bt * KEYD + cbase) = o;
}

// ---------------------------------------------------------------------------
// depthwise causal conv (KS=4) + SiLU for v.  in/out: [B, T, C]
// ---------------------------------------------------------------------------
__global__ void conv_silu_kernel(const float* __restrict__ in,
                                 const float* __restrict__ w,
                                 float* __restrict__ out, int C)
{
    int idx = blockIdx.x * blockDim.x + threadIdx.x;
    int c  = idx % C;
    int bt = idx / C;
    int t  = bt % TSEQ;
    int b  = bt / TSEQ;

    float acc = 0.f;
#pragma unroll
    for (int j = 0; j < KS; j++) {
        int tt = t + j - (KS - 1);
        if (tt >= 0)
            acc = fmaf(w[c * KS + j], in[((size_t)(b * TSEQ + tt)) * C + c], acc);
    }
    out[idx] = acc / (1.f + expf(-acc));   // SiLU
}

// ---------------------------------------------------------------------------
// Recurrent delta-rule scan. State S[b,h,vd,kd] in registers.
// Grid: B*H*(VDIM/32) = 128 CTAs, 256 threads (8 warps).
// Warp handles 4 v-rows; lane = ksub*4 + rowid, ksub in 0..7 owns 16 k's.
// Reductions over KD via 3 shfl_xor (offsets 4,8,16).
// ---------------------------------------------------------------------------
#define VCHUNK 32
__global__ void __launch_bounds__(256) scan_kernel(
    const float* __restrict__ q, const float* __restrict__ k,
    const float* __restrict__ v, const float* __restrict__ alpha,
    const float* __restrict__ beta, float* __restrict__ o)
{
    int bid  = blockIdx.x;
    int vblk = bid & 7;            // 0..7  (VDIM/VCHUNK = 8)
    int h    = (bid >> 3) & 7;
    int b    = bid >> 6;

    int warp  = threadIdx.x >> 5;
    int lane  = threadIdx.x & 31;
    int rowid = lane & 3;
    int ksub  = lane >> 2;
    int vrow  = vblk * VCHUNK + warp * 4 + rowid;   // 0..255 within head

    float S[16];
#pragma unroll
    for (int i = 0; i < 16; i++) S[i] = 0.f;

    const float* kbase = k + (size_t)(b * TSEQ) * KEYD + h * KDIM + ksub * 16;
    const float* qbase = q + (size_t)(b * TSEQ) * KEYD + h * KDIM + ksub * 16;
    const float* vbase = v + (size_t)(b * TSEQ) * VALD + h * VDIM + vrow;
    const float* abase = alpha + (size_t)(b * TSEQ) * HH + h;
    const float* bbase = beta  + (size_t)(b * TSEQ) * HH + h;
    float*       obase = o + (size_t)(b * TSEQ) * VALD + h * VDIM + vrow;

    for (int t = 0; t < TSEQ; t++) {
        float kt[16], qt[16];
        const float4* kp = (const float4*)(kbase + (size_t)t * KEYD);
        const float4* qp = (const float4*)(qbase + (size_t)t * KEYD);
        ((float4*)kt)[0] = kp[0]; ((float4*)kt)[1] = kp[1];
        ((float4*)kt)[2] = kp[2]; ((float4*)kt)[3] = kp[3];
        ((float4*)qt)[0] = qp[0]; ((float4*)qt)[1] = qp[1];
        ((float4*)qt)[2] = qp[2]; ((float4*)qt)[3] = qp[3];

        float a  = abase[(size_t)t * HH];
        float bt = bbase[(size_t)t * HH];
        float vt = vbase[(size_t)t * VALD];

        // retained = S_row . k_t
        float r = 0.f;
#pragma unroll
        for (int i = 0; i < 16; i++) r = fmaf(S[i], kt[i], r);
        r += __shfl_xor_sync(0xffffffffu, r, 4);
        r += __shfl_xor_sync(0xffffffffu, r, 8);
        r += __shfl_xor_sync(0xffffffffu, r, 16);

        float coef = bt * vt - a * bt * r;

        // S = a*S + k_t*coef ; o = S . q_t
        float ov = 0.f;
#pragma unroll
        for (int i = 0; i < 16; i++) {
            S[i] = fmaf(a, S[i], kt[i] * coef);
            ov   = fmaf(S[i], qt[i], ov);
        }
        ov += __shfl_xor_sync(0xffffffffu, ov, 4);
        ov += __shfl_xor_sync(0xffffffffu, ov, 8);
        ov += __shfl_xor_sync(0xffffffffu, ov, 16);

        if (ksub == 0) obase[(size_t)t * VALD] = ov;
    }
}

// ---------------------------------------------------------------------------
// RMS norm over VDIM + weight + SiLU(gate). One warp per (b,t,h).
// ---------------------------------------------------------------------------
__global__ void __launch_bounds__(256) normgate_kernel(
    const float* __restrict__ o, const float* __restrict__ g,
    const float* __restrict__ w, float* __restrict__ y)
{
    int gw   = (blockIdx.x * 256 + threadIdx.x) >> 5;  // (bt*H + h)
    int lane = threadIdx.x & 31;
    const float* op = o + (size_t)gw * VDIM + lane * 8;
    const float* gp = g + (size_t)gw * VDIM + lane * 8;
    float*       yp = y + (size_t)gw * VDIM + lane * 8;

    float vals[8];
    *(float4*)(vals)     = *(const float4*)(op);
    *(float4*)(vals + 4) = *(const float4*)(op + 4);

    float ss = 0.f;
#pragma unroll
    for (int i = 0; i < 8; i++) ss = fmaf(vals[i], vals[i], ss);
#pragma unroll
    for (int off = 16; off > 0; off >>= 1)
        ss += __shfl_xor_sync(0xffffffffu, ss, off);
    float rms = rsqrtf(ss * (1.f / VDIM) + 1e-5f);

    float gv[8];
    *(float4*)(gv)     = *(const float4*)(gp);
    *(float4*)(gv + 4) = *(const float4*)(gp + 4);

    float out[8];
#pragma unroll
    for (int i = 0; i < 8; i++) {
        float gg   = gv[i];
        float silu = gg / (1.f + expf(-gg));
        out[i] = vals[i] * rms * w[lane * 8 + i] * silu;
    }
    *(float4*)(yp)     = *(float4*)(out);
    *(float4*)(yp + 4) = *(float4*)(out + 4);
}

// ---------------------------------------------------------------------------
// Host launcher
// ---------------------------------------------------------------------------
extern "C" void kernel_launch(void* const* d_in, const int* in_sizes, int n_in,
                              void* d_out, int out_size)
{
    const float* x       = (const float*)d_in[0];
    const float* Wq      = (const float*)d_in[1];
    const float* Wk      = (const float*)d_in[2];
    const float* Wv      = (const float*)d_in[3];
    const float* Wa      = (const float*)d_in[4];
    const float* Wb      = (const float*)d_in[5];
    const float* Wg      = (const float*)d_in[6];
    const float* Wo      = (const float*)d_in[7];
    const float* A_log   = (const float*)d_in[8];
    const float* dt_bias = (const float*)d_in[9];
    const float* conv_q  = (const float*)d_in[10];
    const float* conv_k  = (const float*)d_in[11];
    const float* conv_v  = (const float*)d_in[12];
    const float* o_w     = (const float*)d_in[13];
    float* out = (float*)d_out;

    float* arena = nullptr;
    cudaGetSymbolAddress((void**)&arena, g_arena);

    float* qproj = arena + OFF_QPROJ;
    float* kproj = arena + OFF_KPROJ;
    float* vproj = arena + OFF_VPROJ;
    float* gproj = arena + OFF_GPROJ;
    float* qc    = arena + OFF_QC;
    float* kc    = arena + OFF_KC;
    float* vc    = arena + OFF_VC;
    float* al    = arena + OFF_AL;
    float* be    = arena + OFF_BE;
    float* opre  = arena + OFF_OPRE;   // aliases vproj (dead after conv_v)
    float* yn    = arena + OFF_YNORM;  // aliases qproj+kproj (dead after convs)

    dim3 blk(256);

    // projections
    sgemm_kernel<<<dim3(KEYD / 128, NTOK / 128), blk>>>(x, Wq, qproj, NTOK, KEYD, DD);
    sgemm_kernel<<<dim3(KEYD / 128, NTOK / 128), blk>>>(x, Wk, kproj, NTOK, KEYD, DD);
    sgemm_kernel<<<dim3(VALD / 128, NTOK / 128), blk>>>(x, Wv, vproj, NTOK, VALD, DD);
    sgemm_kernel<<<dim3(VALD / 128, NTOK / 128), blk>>>(x, Wg, gproj, NTOK, VALD, DD);

    // alpha/beta
    ab_kernel<<<NTOK, blk>>>(x, Wa, Wb, A_log, dt_bias, al, be);

    // conv + silu (+ l2norm for q/k, fused)
    conv_silu_l2_kernel<<<(NTOK * HH) / 8, blk>>>(qproj, conv_q, qc);
    conv_silu_l2_kernel<<<(NTOK * HH) / 8, blk>>>(kproj, conv_k, kc);
    conv_silu_kernel<<<(NTOK * VALD) / 256, blk>>>(vproj, conv_v, vc, VALD);

    // recurrent scan (opre aliases vproj — vproj fully consumed by conv_v above)
    scan_kernel<<<BB * HH * (VDIM / VCHUNK), blk>>>(qc, kc, vc, al, be, opre);

    // rms norm + gate (yn aliases qproj/kproj — dead after convs)
    normgate_kernel<<<(NTOK * HH) / 8, blk>>>(opre, gproj, o_w, yn);

    // output projection
    sgemm_kernel<<<dim3(DD / 128, NTOK / 128), blk>>>(yn, Wo, out, NTOK, DD, VALD);
}

// round 4
// speedup vs baseline: 1.3932x; 1.3932x over previous
#include <cuda_runtime.h>
#include <math.h>
#include <stdint.h>

// ---------------------------------------------------------------------------
// Problem constants (match reference)
// ---------------------------------------------------------------------------
#define BB    2
#define TSEQ  2048
#define DD    1024
#define HH    8
#define KDIM  128
#define VDIM  256
#define KEYD  1024          // H*KDIM
#define VALD  2048          // H*VDIM
#define NTOK  (BB*TSEQ)     // 4096
#define KS    4

// ---------------------------------------------------------------------------
// Scratch arena (device global — no allocation allowed)
// ---------------------------------------------------------------------------
#define OFF_QPROJ  (size_t)0                         // 4M floats
#define OFF_KPROJ  (OFF_QPROJ + (size_t)NTOK*KEYD)   // +4M
#define OFF_VPROJ  (OFF_KPROJ + (size_t)NTOK*KEYD)   // +8M
#define OFF_GPROJ  (OFF_VPROJ + (size_t)NTOK*VALD)   // +8M
#define OFF_QC     (OFF_GPROJ + (size_t)NTOK*VALD)   // +4M
#define OFF_KC     (OFF_QC    + (size_t)NTOK*KEYD)   // +4M
#define OFF_VC     (OFF_KC    + (size_t)NTOK*KEYD)   // +8M
#define OFF_AL     (OFF_VC    + (size_t)NTOK*VALD)
#define OFF_BE     (OFF_AL    + (size_t)NTOK*HH)
#define ARENA_F    (OFF_BE    + (size_t)NTOK*HH)
#define OFF_OPRE   OFF_VPROJ    // vproj dead after conv_v
#define OFF_YNORM  OFF_QPROJ    // qproj+kproj dead after conv_q/k

__device__ float g_arena[ARENA_F];

// ---------------------------------------------------------------------------
// TF32 helpers
// ---------------------------------------------------------------------------
__device__ __forceinline__ uint32_t f2tf32(float x) {
    uint32_t r;
    asm("cvt.rna.tf32.f32 %0, %1;" : "=r"(r) : "f"(x));
    return r;
}

__device__ __forceinline__ void mma_tf32(float* c, const uint32_t* a, const uint32_t* b) {
    asm volatile(
        "mma.sync.aligned.m16n8k8.row.col.f32.tf32.tf32.f32 "
        "{%0,%1,%2,%3}, {%4,%5,%6,%7}, {%8,%9}, {%0,%1,%2,%3};"
        : "+f"(c[0]), "+f"(c[1]), "+f"(c[2]), "+f"(c[3])
        : "r"(a[0]), "r"(a[1]), "r"(a[2]), "r"(a[3]), "r"(b[0]), "r"(b[1]));
}

__device__ __forceinline__ void cp16(uint32_t smem_dst, const void* gsrc) {
    asm volatile("cp.async.cg.shared.global [%0], [%1], 16;" :: "r"(smem_dst), "l"(gsrc));
}

// ---------------------------------------------------------------------------
// TF32 tensor-core GEMM: C[M,N] = A[M,K] @ B[K,N], all row-major, fp32 I/O.
// BM=128, BN=128, BK=16, 256 threads (8 warps, 2x4), warp tile 64x32.
// Double-buffered cp.async pipeline. M,N,K multiples of 128.
// Padded smem: A stride 20 floats, B stride 136 floats (both conflict-free
// for the m16n8k8 fragment access patterns, both 16B-aligned row strides).
// ---------------------------------------------------------------------------
#define GA_STRIDE 20
#define GB_STRIDE 136

__global__ void __launch_bounds__(256) tf32gemm_kernel(
    const float* __restrict__ A, const float* __restrict__ B,
    float* __restrict__ C, int M, int N, int K)
{
    __shared__ float As[2][128 * GA_STRIDE];
    __shared__ float Bs[2][16 * GB_STRIDE];

    const int tid  = threadIdx.x;
    const int bm   = blockIdx.y, bn = blockIdx.x;
    const int warp = tid >> 5, lane = tid & 31;
    const int wm   = (warp >> 2) * 64;       // warp row offset in tile
    const int wn   = (warp & 3) * 32;        // warp col offset in tile
    const int gid  = lane >> 2;              // 0..7
    const int tg   = lane & 3;               // 0..3

    // loader coordinates
    const int a_r0 = tid >> 2;               // 0..63
    const int a_c  = (tid & 3) * 4;          // 0,4,8,12
    const int b_r0 = tid >> 5;               // 0..7
    const int b_c  = (tid & 31) * 4;         // 0..124

    const float* Ag = A + (size_t)(bm * 128) * K;
    const float* Bg = B + (size_t)bn * 128;

    uint32_t as_base = (uint32_t)__cvta_generic_to_shared(&As[0][0]);
    uint32_t bs_base = (uint32_t)__cvta_generic_to_shared(&Bs[0][0]);
    const uint32_t as_buf = 128 * GA_STRIDE * 4;
    const uint32_t bs_buf = 16 * GB_STRIDE * 4;

    float acc[4][4][4];
#pragma unroll
    for (int i = 0; i < 4; i++)
#pragma unroll
        for (int j = 0; j < 4; j++)
#pragma unroll
            for (int r = 0; r < 4; r++) acc[i][j][r] = 0.f;

    const int niter = K >> 4;   // BK = 16

    // prefetch iteration 0 into buffer 0
    {
#pragma unroll
        for (int f = 0; f < 2; f++) {
            int row = f * 64 + a_r0;
            cp16(as_base + (uint32_t)((row * GA_STRIDE + a_c) << 2),
                 Ag + (size_t)row * K + a_c);
        }
#pragma unroll
        for (int f = 0; f < 2; f++) {
            int row = f * 8 + b_r0;
            cp16(bs_base + (uint32_t)((row * GB_STRIDE + b_c) << 2),
                 Bg + (size_t)row * N + b_c);
        }
        asm volatile("cp.async.commit_group;");
    }

    for (int it = 0; it < niter; it++) {
        const int p = it & 1;

        if (it + 1 < niter) {
            const int k0 = (it + 1) << 4;
            const uint32_t ao = as_base + (p ^ 1) * as_buf;
            const uint32_t bo = bs_base + (p ^ 1) * bs_buf;
#pragma unroll
            for (int f = 0; f < 2; f++) {
                int row = f * 64 + a_r0;
                cp16(ao + (uint32_t)((row * GA_STRIDE + a_c) << 2),
                     Ag + (size_t)row * K + k0 + a_c);
            }
#pragma unroll
            for (int f = 0; f < 2; f++) {
                int row = f * 8 + b_r0;
                cp16(bo + (uint32_t)((row * GB_STRIDE + b_c) << 2),
                     Bg + (size_t)(k0 + row) * N + b_c);
            }
            asm volatile("cp.async.commit_group;");
            asm volatile("cp.async.wait_group 1;");
        } else {
            asm volatile("cp.async.wait_group 0;");
        }
        __syncthreads();

        const float* Ap = As[p];
        const float* Bp = Bs[p];

#pragma unroll
        for (int ks = 0; ks < 2; ks++) {
            uint32_t af[4][4];
#pragma unroll
            for (int mt = 0; mt < 4; mt++) {
                int r = wm + mt * 16 + gid;
                int c = ks * 8 + tg;
                af[mt][0] = f2tf32(Ap[r * GA_STRIDE + c]);
                af[mt][1] = f2tf32(Ap[(r + 8) * GA_STRIDE + c]);
                af[mt][2] = f2tf32(Ap[r * GA_STRIDE + c + 4]);
                af[mt][3] = f2tf32(Ap[(r + 8) * GA_STRIDE + c + 4]);
            }
            uint32_t bf[4][2];
#pragma unroll
            for (int nt = 0; nt < 4; nt++) {
                int n = wn + nt * 8 + gid;
                bf[nt][0] = f2tf32(Bp[(ks * 8 + tg) * GB_STRIDE + n]);
                bf[nt][1] = f2tf32(Bp[(ks * 8 + 4 + tg) * GB_STRIDE + n]);
            }
#pragma unroll
            for (int mt = 0; mt < 4; mt++)
#pragma unroll
                for (int nt = 0; nt < 4; nt++)
                    mma_tf32(acc[mt][nt], af[mt], bf[nt]);
        }
        __syncthreads();
    }

    // epilogue: each thread owns 2 rows x 2 cols per (mt,nt)
#pragma unroll
    for (int mt = 0; mt < 4; mt++) {
        int r0 = bm * 128 + wm + mt * 16 + gid;
#pragma unroll
        for (int nt = 0; nt < 4; nt++) {
            int c0 = bn * 128 + wn + nt * 8 + tg * 2;
            *(float2*)(C + (size_t)r0 * N + c0)       = make_float2(acc[mt][nt][0], acc[mt][nt][1]);
            *(float2*)(C + (size_t)(r0 + 8) * N + c0) = make_float2(acc[mt][nt][2], acc[mt][nt][3]);
        }
    }
}

// ---------------------------------------------------------------------------
// a/b projections (N=8 each) + alpha/beta transforms, one token per block
// ---------------------------------------------------------------------------
__global__ void __launch_bounds__(256) ab_kernel(
    const float* __restrict__ x, const float* __restrict__ Wa,
    const float* __restrict__ Wb, const float* __restrict__ A_log,
    const float* __restrict__ dt_bias,
    float* __restrict__ alpha, float* __restrict__ beta)
{
    __shared__ float xs[DD];
    int t = blockIdx.x;
    for (int i = threadIdx.x; i < DD; i += 256)
        xs[i] = x[(size_t)t * DD + i];
    __syncthreads();

    int warp = threadIdx.x >> 5;     // 0..7 == head
    int lane = threadIdx.x & 31;

    float sa = 0.f, sb = 0.f;
    for (int kk = lane; kk < DD; kk += 32) {
        float xv = xs[kk];
        sa = fmaf(xv, Wa[kk * HH + warp], sa);
        sb = fmaf(xv, Wb[kk * HH + warp], sb);
    }
#pragma unroll
    for (int off = 16; off > 0; off >>= 1) {
        sa += __shfl_xor_sync(0xffffffffu, sa, off);
        sb += __shfl_xor_sync(0xffffffffu, sb, off);
    }
    if (lane == 0) {
        float z  = sa + dt_bias[warp];
        float sp = (z > 20.f) ? z : log1pf(expf(z));
        alpha[t * HH + warp] = expf(-expf(A_log[warp]) * sp);
        beta [t * HH + warp] = 2.f / (1.f + expf(-sb));
    }
}

// ---------------------------------------------------------------------------
// Fused depthwise causal conv (KS=4) + SiLU + l2norm for q/k.
// One warp per (token, head): lane owns 4 channels (float4).
// ---------------------------------------------------------------------------
__global__ void __launch_bounds__(256) conv_silu_l2_kernel(
    const float* __restrict__ in,   // [NTOK, KEYD] pre-conv
    const float* __restrict__ w,    // [KEYD, KS]
    float* __restrict__ out)        // [NTOK, KEYD] normalized
{
    int gw   = (blockIdx.x * 256 + threadIdx.x) >> 5;  // 0 .. NTOK*HH-1
    int lane = threadIdx.x & 31;
    int h    = gw % HH;
    int bt   = gw / HH;
    int t    = bt % TSEQ;
    int b    = bt / TSEQ;

    int cbase = h * KDIM + lane * 4;

    float acc[4] = {0.f, 0.f, 0.f, 0.f};
    float wt[4][KS];
#pragma unroll
    for (int c = 0; c < 4; c++)
#pragma unroll
        for (int j = 0; j < KS; j++)
            wt[c][j] = w[(cbase + c) * KS + j];

#pragma unroll
    for (int j = 0; j < KS; j++) {
        int tt = t + j - (KS - 1);
        if (tt >= 0) {
            float4 xv = *(const float4*)(in + ((size_t)(b * TSEQ + tt)) * KEYD + cbase);
#pragma unroll
            for (int c = 0; c < 4; c++) {
                float x = (&xv.x)[c];
                acc[c] = fmaf(wt[c][j], x, acc[c]);
            }
        }
    }

    float ss = 0.f;
#pragma unroll
    for (int c = 0; c < 4; c++) {
        acc[c] = acc[c] / (1.f + expf(-acc[c]));   // SiLU
        ss = fmaf(acc[c], acc[c], ss);
    }
#pragma unroll
    for (int off = 16; off > 0; off >>= 1)
        ss += __shfl_xor_sync(0xffffffffu, ss, off);
    float s = 1.f / fmaxf(sqrtf(ss), 1e-6f);

    float4 o;
#pragma unroll
    for (int c = 0; c < 4; c++) (&o.x)[c] = acc[c] * s;
    *(float4*)(out + (size_t)bt * KEYD + cbase) = o;
}

// ---------------------------------------------------------------------------
// depthwise causal conv (KS=4) + SiLU for v.  in/out: [B, T, C]
// ---------------------------------------------------------------------------
__global__ void conv_silu_kernel(const float* __restrict__ in,
                                 const float* __restrict__ w,
                                 float* __restrict__ out, int C)
{
    int idx = blockIdx.x * blockDim.x + threadIdx.x;
    int c  = idx % C;
    int bt = idx / C;
    int t  = bt % TSEQ;
    int b  = bt / TSEQ;

    float acc = 0.f;
#pragma unroll
    for (int j = 0; j < KS; j++) {
        int tt = t + j - (KS - 1);
        if (tt >= 0)
            acc = fmaf(w[c * KS + j], in[((size_t)(b * TSEQ + tt)) * C + c], acc);
    }
    out[idx] = acc / (1.f + expf(-acc));   // SiLU
}

// ---------------------------------------------------------------------------
// Recurrent delta-rule scan. State S[b,h,vd,kd] in registers.
// Grid: B*H*(VDIM/32) = 128 CTAs, 256 threads (8 warps).
// ---------------------------------------------------------------------------
#define VCHUNK 32
__global__ void __launch_bounds__(256) scan_kernel(
    const float* __restrict__ q, const float* __restrict__ k,
    const float* __restrict__ v, const float* __restrict__ alpha,
    const float* __restrict__ beta, float* __restrict__ o)
{
    int bid  = blockIdx.x;
    int vblk = bid & 7;            // 0..7  (VDIM/VCHUNK = 8)
    int h    = (bid >> 3) & 7;
    int b    = bid >> 6;

    int warp  = threadIdx.x >> 5;
    int lane  = threadIdx.x & 31;
    int rowid = lane & 3;
    int ksub  = lane >> 2;
    int vrow  = vblk * VCHUNK + warp * 4 + rowid;   // 0..255 within head

    float S[16];
#pragma unroll
    for (int i = 0; i < 16; i++) S[i] = 0.f;

    const float* kbase = k + (size_t)(b * TSEQ) * KEYD + h * KDIM + ksub * 16;
    const float* qbase = q + (size_t)(b * TSEQ) * KEYD + h * KDIM + ksub * 16;
    const float* vbase = v + (size_t)(b * TSEQ) * VALD + h * VDIM + vrow;
    const float* abase = alpha + (size_t)(b * TSEQ) * HH + h;
    const float* bbase = beta  + (size_t)(b * TSEQ) * HH + h;
    float*       obase = o + (size_t)(b * TSEQ) * VALD + h * VDIM + vrow;

    for (int t = 0; t < TSEQ; t++) {
        float kt[16], qt[16];
        const float4* kp = (const float4*)(kbase + (size_t)t * KEYD);
        const float4* qp = (const float4*)(qbase + (size_t)t * KEYD);
        ((float4*)kt)[0] = kp[0]; ((float4*)kt)[1] = kp[1];
        ((float4*)kt)[2] = kp[2]; ((float4*)kt)[3] = kp[3];
        ((float4*)qt)[0] = qp[0]; ((float4*)qt)[1] = qp[1];
        ((float4*)qt)[2] = qp[2]; ((float4*)qt)[3] = qp[3];

        float a  = abase[(size_t)t * HH];
        float bt = bbase[(size_t)t * HH];
        float vt = vbase[(size_t)t * VALD];

        float r = 0.f;
#pragma unroll
        for (int i = 0; i < 16; i++) r = fmaf(S[i], kt[i], r);
        r += __shfl_xor_sync(0xffffffffu, r, 4);
        r += __shfl_xor_sync(0xffffffffu, r, 8);
        r += __shfl_xor_sync(0xffffffffu, r, 16);

        float coef = bt * vt - a * bt * r;

        float ov = 0.f;
#pragma unroll
        for (int i = 0; i < 16; i++) {
            S[i] = fmaf(a, S[i], kt[i] * coef);
            ov   = fmaf(S[i], qt[i], ov);
        }
        ov += __shfl_xor_sync(0xffffffffu, ov, 4);
        ov += __shfl_xor_sync(0xffffffffu, ov, 8);
        ov += __shfl_xor_sync(0xffffffffu, ov, 16);

        if (ksub == 0) obase[(size_t)t * VALD] = ov;
    }
}

// ---------------------------------------------------------------------------
// RMS norm over VDIM + weight + SiLU(gate). One warp per (b,t,h).
// ---------------------------------------------------------------------------
__global__ void __launch_bounds__(256) normgate_kernel(
    const float* __restrict__ o, const float* __restrict__ g,
    const float* __restrict__ w, float* __restrict__ y)
{
    int gw   = (blockIdx.x * 256 + threadIdx.x) >> 5;  // (bt*H + h)
    int lane = threadIdx.x & 31;
    const float* op = o + (size_t)gw * VDIM + lane * 8;
    const float* gp = g + (size_t)gw * VDIM + lane * 8;
    float*       yp = y + (size_t)gw * VDIM + lane * 8;

    float vals[8];
    *(float4*)(vals)     = *(const float4*)(op);
    *(float4*)(vals + 4) = *(const float4*)(op + 4);

    float ss = 0.f;
#pragma unroll
    for (int i = 0; i < 8; i++) ss = fmaf(vals[i], vals[i], ss);
#pragma unroll
    for (int off = 16; off > 0; off >>= 1)
        ss += __shfl_xor_sync(0xffffffffu, ss, off);
    float rms = rsqrtf(ss * (1.f / VDIM) + 1e-5f);

    float gv[8];
    *(float4*)(gv)     = *(const float4*)(gp);
    *(float4*)(gv + 4) = *(const float4*)(gp + 4);

    float out[8];
#pragma unroll
    for (int i = 0; i < 8; i++) {
        float gg   = gv[i];
        float silu = gg / (1.f + expf(-gg));
        out[i] = vals[i] * rms * w[lane * 8 + i] * silu;
    }
    *(float4*)(yp)     = *(float4*)(out);
    *(float4*)(yp + 4) = *(float4*)(out + 4);
}

// ---------------------------------------------------------------------------
// Host launcher
// ---------------------------------------------------------------------------
extern "C" void kernel_launch(void* const* d_in, const int* in_sizes, int n_in,
                              void* d_out, int out_size)
{
    const float* x       = (const float*)d_in[0];
    const float* Wq      = (const float*)d_in[1];
    const float* Wk      = (const float*)d_in[2];
    const float* Wv      = (const float*)d_in[3];
    const float* Wa      = (const float*)d_in[4];
    const float* Wb      = (const float*)d_in[5];
    const float* Wg      = (const float*)d_in[6];
    const float* Wo      = (const float*)d_in[7];
    const float* A_log   = (const float*)d_in[8];
    const float* dt_bias = (const float*)d_in[9];
    const float* conv_q  = (const float*)d_in[10];
    const float* conv_k  = (const float*)d_in[11];
    const float* conv_v  = (const float*)d_in[12];
    const float* o_w     = (const float*)d_in[13];
    float* out = (float*)d_out;

    float* arena = nullptr;
    cudaGetSymbolAddress((void**)&arena, g_arena);

    float* qproj = arena + OFF_QPROJ;
    float* kproj = arena + OFF_KPROJ;
    float* vproj = arena + OFF_VPROJ;
    float* gproj = arena + OFF_GPROJ;
    float* qc    = arena + OFF_QC;
    float* kc    = arena + OFF_KC;
    float* vc    = arena + OFF_VC;
    float* al    = arena + OFF_AL;
    float* be    = arena + OFF_BE;
    float* opre  = arena + OFF_OPRE;   // aliases vproj (dead after conv_v)
    float* yn    = arena + OFF_YNORM;  // aliases qproj/kproj (dead after convs)

    dim3 blk(256);

    // projections (TF32 tensor cores)
    tf32gemm_kernel<<<dim3(KEYD / 128, NTOK / 128), blk>>>(x, Wq, qproj, NTOK, KEYD, DD);
    tf32gemm_kernel<<<dim3(KEYD / 128, NTOK / 128), blk>>>(x, Wk, kproj, NTOK, KEYD, DD);
    tf32gemm_kernel<<<dim3(VALD / 128, NTOK / 128), blk>>>(x, Wv, vproj, NTOK, VALD, DD);
    tf32gemm_kernel<<<dim3(VALD / 128, NTOK / 128), blk>>>(x, Wg, gproj, NTOK, VALD, DD);

    // alpha/beta
    ab_kernel<<<NTOK, blk>>>(x, Wa, Wb, A_log, dt_bias, al, be);

    // conv + silu (+ l2norm for q/k, fused)
    conv_silu_l2_kernel<<<(NTOK * HH) / 8, blk>>>(qproj, conv_q, qc);
    conv_silu_l2_kernel<<<(NTOK * HH) / 8, blk>>>(kproj, conv_k, kc);
    conv_silu_kernel<<<(NTOK * VALD) / 256, blk>>>(vproj, conv_v, vc, VALD);

    // recurrent scan (opre aliases vproj — fully consumed by conv_v above)
    scan_kernel<<<BB * HH * (VDIM / VCHUNK), blk>>>(qc, kc, vc, al, be, opre);

    // rms norm + gate (yn aliases qproj/kproj — dead after convs)
    normgate_kernel<<<(NTOK * HH) / 8, blk>>>(opre, gproj, o_w, yn);

    // output projection
    tf32gemm_kernel<<<dim3(DD / 128, NTOK / 128), blk>>>(yn, Wo, out, NTOK, DD, VALD);
}

// round 5
// speedup vs baseline: 2.2952x; 1.6475x over previous
#include <cuda_runtime.h>
#include <math.h>
#include <stdint.h>

// ---------------------------------------------------------------------------
// Problem constants
// ---------------------------------------------------------------------------
#define BB    2
#define TSEQ  2048
#define DD    1024
#define HH    8
#define KDIM  128
#define VDIM  256
#define KEYD  1024          // H*KDIM
#define VALD  2048          // H*VDIM
#define NTOK  (BB*TSEQ)     // 4096
#define KS    4
#define PS    6144          // packed projection row stride (q|k|v|g)
#define QO    0
#define KO    1024
#define VO    2048
#define GO    4096

// ---------------------------------------------------------------------------
// Scratch arena (device global — no allocation allowed)
// ---------------------------------------------------------------------------
static constexpr size_t OFF_WPACK = 0;                                    // [1024][6144]
static constexpr size_t OFF_PROJ  = OFF_WPACK + (size_t)DD * PS;          // [4096][6144]
static constexpr size_t OFF_QC    = OFF_PROJ  + (size_t)NTOK * PS;        // [4096][1024]
static constexpr size_t OFF_KC    = OFF_QC    + (size_t)NTOK * KEYD;      // [4096][1024]
static constexpr size_t OFF_VC    = OFF_KC    + (size_t)NTOK * KEYD;      // [4096][2048]
static constexpr size_t OFF_AL    = OFF_VC    + (size_t)NTOK * VALD;
static constexpr size_t OFF_BE    = OFF_AL    + (size_t)NTOK * HH;
static constexpr size_t OFF_WABT  = OFF_BE    + (size_t)NTOK * HH;        // [2][8][1024]
static constexpr size_t OFF_OPART = OFF_WABT  + (size_t)2 * HH * DD;      // [NTOK*HH][8][256]
static constexpr size_t OFF_YN    = OFF_OPART + (size_t)NTOK * HH * 8 * VDIM;
static constexpr size_t ARENA_F   = OFF_YN    + (size_t)NTOK * VALD;

__device__ float g_arena[ARENA_F];

// ---------------------------------------------------------------------------
// TF32 helpers
// ---------------------------------------------------------------------------
__device__ __forceinline__ uint32_t f2tf32(float x) {
    uint32_t r;
    asm("cvt.rna.tf32.f32 %0, %1;" : "=r"(r) : "f"(x));
    return r;
}

__device__ __forceinline__ void mma_tf32(float* c, const uint32_t* a, const uint32_t* b) {
    asm volatile(
        "mma.sync.aligned.m16n8k8.row.col.f32.tf32.tf32.f32 "
        "{%0,%1,%2,%3}, {%4,%5,%6,%7}, {%8,%9}, {%0,%1,%2,%3};"
        : "+f"(c[0]), "+f"(c[1]), "+f"(c[2]), "+f"(c[3])
        : "r"(a[0]), "r"(a[1]), "r"(a[2]), "r"(a[3]), "r"(b[0]), "r"(b[1]));
}

__device__ __forceinline__ void cp16(uint32_t smem_dst, const void* gsrc) {
    asm volatile("cp.async.cg.shared.global [%0], [%1], 16;" :: "r"(smem_dst), "l"(gsrc));
}

// ---------------------------------------------------------------------------
// TF32 tensor-core GEMM: C[M,N] = A[M,K] @ B[K,N], row-major, fp32 I/O.
// BM=128, BN=128, BK=16, 256 threads (8 warps 2x4), warp tile 64x32,
// double-buffered cp.async. M,N,K multiples of 128.
// ---------------------------------------------------------------------------
#define GA_STRIDE 20
#define GB_STRIDE 136

__global__ void __launch_bounds__(256) tf32gemm_kernel(
    const float* __restrict__ A, const float* __restrict__ B,
    float* __restrict__ C, int M, int N, int K)
{
    __shared__ float As[2][128 * GA_STRIDE];
    __shared__ float Bs[2][16 * GB_STRIDE];

    const int tid  = threadIdx.x;
    const int bm   = blockIdx.y, bn = blockIdx.x;
    const int warp = tid >> 5, lane = tid & 31;
    const int wm   = (warp >> 2) * 64;
    const int wn   = (warp & 3) * 32;
    const int gid  = lane >> 2;
    const int tg   = lane & 3;

    const int a_r0 = tid >> 2;
    const int a_c  = (tid & 3) * 4;
    const int b_r0 = tid >> 5;
    const int b_c  = (tid & 31) * 4;

    const float* Ag = A + (size_t)(bm * 128) * K;
    const float* Bg = B + (size_t)bn * 128;

    uint32_t as_base = (uint32_t)__cvta_generic_to_shared(&As[0][0]);
    uint32_t bs_base = (uint32_t)__cvta_generic_to_shared(&Bs[0][0]);
    const uint32_t as_buf = 128 * GA_STRIDE * 4;
    const uint32_t bs_buf = 16 * GB_STRIDE * 4;

    float acc[4][4][4];
#pragma unroll
    for (int i = 0; i < 4; i++)
#pragma unroll
        for (int j = 0; j < 4; j++)
#pragma unroll
            for (int r = 0; r < 4; r++) acc[i][j][r] = 0.f;

    const int niter = K >> 4;

    {
#pragma unroll
        for (int f = 0; f < 2; f++) {
            int row = f * 64 + a_r0;
            cp16(as_base + (uint32_t)((row * GA_STRIDE + a_c) << 2),
                 Ag + (size_t)row * K + a_c);
        }
#pragma unroll
        for (int f = 0; f < 2; f++) {
            int row = f * 8 + b_r0;
            cp16(bs_base + (uint32_t)((row * GB_STRIDE + b_c) << 2),
                 Bg + (size_t)row * N + b_c);
        }
        asm volatile("cp.async.commit_group;");
    }

    for (int it = 0; it < niter; it++) {
        const int p = it & 1;

        if (it + 1 < niter) {
            const int k0 = (it + 1) << 4;
            const uint32_t ao = as_base + (p ^ 1) * as_buf;
            const uint32_t bo = bs_base + (p ^ 1) * bs_buf;
#pragma unroll
            for (int f = 0; f < 2; f++) {
                int row = f * 64 + a_r0;
                cp16(ao + (uint32_t)((row * GA_STRIDE + a_c) << 2),
                     Ag + (size_t)row * K + k0 + a_c);
            }
#pragma unroll
            for (int f = 0; f < 2; f++) {
                int row = f * 8 + b_r0;
                cp16(bo + (uint32_t)((row * GB_STRIDE + b_c) << 2),
                     Bg + (size_t)(k0 + row) * N + b_c);
            }
            asm volatile("cp.async.commit_group;");
            asm volatile("cp.async.wait_group 1;");
        } else {
            asm volatile("cp.async.wait_group 0;");
        }
        __syncthreads();

        const float* Ap = As[p];
        const float* Bp = Bs[p];

#pragma unroll
        for (int ks = 0; ks < 2; ks++) {
            uint32_t af[4][4];
#pragma unroll
            for (int mt = 0; mt < 4; mt++) {
                int r = wm + mt * 16 + gid;
                int c = ks * 8 + tg;
                af[mt][0] = f2tf32(Ap[r * GA_STRIDE + c]);
                af[mt][1] = f2tf32(Ap[(r + 8) * GA_STRIDE + c]);
                af[mt][2] = f2tf32(Ap[r * GA_STRIDE + c + 4]);
                af[mt][3] = f2tf32(Ap[(r + 8) * GA_STRIDE + c + 4]);
            }
            uint32_t bf[4][2];
#pragma unroll
            for (int nt = 0; nt < 4; nt++) {
                int n = wn + nt * 8 + gid;
                bf[nt][0] = f2tf32(Bp[(ks * 8 + tg) * GB_STRIDE + n]);
                bf[nt][1] = f2tf32(Bp[(ks * 8 + 4 + tg) * GB_STRIDE + n]);
            }
#pragma unroll
            for (int mt = 0; mt < 4; mt++)
#pragma unroll
                for (int nt = 0; nt < 4; nt++)
                    mma_tf32(acc[mt][nt], af[mt], bf[nt]);
        }
        __syncthreads();
    }

#pragma unroll
    for (int mt = 0; mt < 4; mt++) {
        int r0 = bm * 128 + wm + mt * 16 + gid;
#pragma unroll
        for (int nt = 0; nt < 4; nt++) {
            int c0 = bn * 128 + wn + nt * 8 + tg * 2;
            *(float2*)(C + (size_t)r0 * N + c0)       = make_float2(acc[mt][nt][0], acc[mt][nt][1]);
            *(float2*)(C + (size_t)(r0 + 8) * N + c0) = make_float2(acc[mt][nt][2], acc[mt][nt][3]);
        }
    }
}

// ---------------------------------------------------------------------------
// Weight packing: Wpack[k][0:6144] = Wq|Wk|Wv|Wg row k
// ---------------------------------------------------------------------------
__global__ void __launch_bounds__(256) pack_w_kernel(
    const float* __restrict__ Wq, const float* __restrict__ Wk,
    const float* __restrict__ Wv, const float* __restrict__ Wg,
    float* __restrict__ Wp)
{
    int idx = blockIdx.x * 256 + threadIdx.x;
    int col = idx % PS, k = idx / PS;
    float v;
    if (col < 1024)      v = Wq[k * 1024 + col];
    else if (col < 2048) v = Wk[k * 1024 + col - 1024];
    else if (col < 4096) v = Wv[k * 2048 + col - 2048];
    else                 v = Wg[k * 2048 + col - 4096];
    Wp[idx] = v;
}

// WabT[0][h][k] = Wa[k*8+h], WabT[1][h][k] = Wb[k*8+h]
__global__ void __launch_bounds__(256) pack_ab_kernel(
    const float* __restrict__ Wa, const float* __restrict__ Wb,
    float* __restrict__ WT)
{
    int idx = blockIdx.x * 256 + threadIdx.x;      // 0..16383
    int k = idx & 1023, h = (idx >> 10) & 7, a = idx >> 13;
    WT[idx] = a ? Wb[k * 8 + h] : Wa[k * 8 + h];
}

// ---------------------------------------------------------------------------
// alpha/beta: one token per block, warp = head, coalesced transposed weights
// ---------------------------------------------------------------------------
__global__ void __launch_bounds__(256) ab_kernel(
    const float* __restrict__ x, const float* __restrict__ WT,
    const float* __restrict__ A_log, const float* __restrict__ dt_bias,
    float* __restrict__ alpha, float* __restrict__ beta)
{
    __shared__ float xs[DD];
    int t = blockIdx.x;
    for (int i = threadIdx.x; i < DD; i += 256)
        xs[i] = x[(size_t)t * DD + i];
    __syncthreads();

    int warp = threadIdx.x >> 5;     // head
    int lane = threadIdx.x & 31;
    const float* wa = WT + warp * 1024;
    const float* wb = WT + 8192 + warp * 1024;

    float sa = 0.f, sb = 0.f;
#pragma unroll 4
    for (int kk = lane; kk < DD; kk += 32) {
        float xv = xs[kk];
        sa = fmaf(xv, wa[kk], sa);
        sb = fmaf(xv, wb[kk], sb);
    }
#pragma unroll
    for (int off = 16; off > 0; off >>= 1) {
        sa += __shfl_xor_sync(0xffffffffu, sa, off);
        sb += __shfl_xor_sync(0xffffffffu, sb, off);
    }
    if (lane == 0) {
        float z  = sa + dt_bias[warp];
        float sp = (z > 20.f) ? z : log1pf(expf(z));
        alpha[t * HH + warp] = expf(-expf(A_log[warp]) * sp);
        beta [t * HH + warp] = 2.f / (1.f + expf(-sb));
    }
}

// ---------------------------------------------------------------------------
// Fused depthwise causal conv (KS=4) + SiLU + l2norm for q/k.
// One warp per (token, head); input has row stride PS (packed proj).
// ---------------------------------------------------------------------------
__global__ void __launch_bounds__(256) conv_silu_l2_kernel(
    const float* __restrict__ in,   // PROJ + col offset; rows stride PS
    const float* __restrict__ w,    // [KEYD, KS]
    float* __restrict__ out)        // [NTOK, KEYD]
{
    int gw   = (blockIdx.x * 256 + threadIdx.x) >> 5;
    int lane = threadIdx.x & 31;
    int h    = gw % HH;
    int bt   = gw / HH;
    int t    = bt % TSEQ;
    int b    = bt / TSEQ;

    int cbase = h * KDIM + lane * 4;

    float acc[4] = {0.f, 0.f, 0.f, 0.f};
    float wt[4][KS];
#pragma unroll
    for (int c = 0; c < 4; c++)
#pragma unroll
        for (int j = 0; j < KS; j++)
            wt[c][j] = w[(cbase + c) * KS + j];

#pragma unroll
    for (int j = 0; j < KS; j++) {
        int tt = t + j - (KS - 1);
        if (tt >= 0) {
            float4 xv = *(const float4*)(in + ((size_t)(b * TSEQ + tt)) * PS + cbase);
#pragma unroll
            for (int c = 0; c < 4; c++)
                acc[c] = fmaf(wt[c][j], (&xv.x)[c], acc[c]);
        }
    }

    float ss = 0.f;
#pragma unroll
    for (int c = 0; c < 4; c++) {
        acc[c] = acc[c] / (1.f + expf(-acc[c]));
        ss = fmaf(acc[c], acc[c], ss);
    }
#pragma unroll
    for (int off = 16; off > 0; off >>= 1)
        ss += __shfl_xor_sync(0xffffffffu, ss, off);
    float s = 1.f / fmaxf(sqrtf(ss), 1e-6f);

    float4 o;
#pragma unroll
    for (int c = 0; c < 4; c++) (&o.x)[c] = acc[c] * s;
    *(float4*)(out + (size_t)bt * KEYD + cbase) = o;
}

// ---------------------------------------------------------------------------
// depthwise causal conv (KS=4) + SiLU for v; input row stride PS
// ---------------------------------------------------------------------------
__global__ void conv_silu_kernel(const float* __restrict__ in,
                                 const float* __restrict__ w,
                                 float* __restrict__ out)
{
    int idx = blockIdx.x * blockDim.x + threadIdx.x;   // over NTOK*VALD
    int c  = idx % VALD;
    int bt = idx / VALD;
    int t  = bt % TSEQ;
    int b  = bt / TSEQ;

    float acc = 0.f;
#pragma unroll
    for (int j = 0; j < KS; j++) {
        int tt = t + j - (KS - 1);
        if (tt >= 0)
            acc = fmaf(w[c * KS + j], in[((size_t)(b * TSEQ + tt)) * PS + c], acc);
    }
    out[idx] = acc / (1.f + expf(-acc));
}

// ---------------------------------------------------------------------------
// Recurrent delta-rule scan. State in registers; 128 CTAs x 256 threads.
// Warp: 4 v-rows, lane = ksub*4 + rowid; ksub owns 16 k's.
// Output: per-ksub PARTIALS to opart[(bt*H+h)][ksub][vrow]; no output shfls.
// Distance-2 register prefetch of q/k/v/alpha/beta.
// ---------------------------------------------------------------------------
#define VCHUNK 32

__global__ void __launch_bounds__(256) scan_kernel(
    const float* __restrict__ q, const float* __restrict__ k,
    const float* __restrict__ v, const float* __restrict__ alpha,
    const float* __restrict__ beta, float* __restrict__ opart)
{
    int bid  = blockIdx.x;
    int vblk = bid & 7;
    int h    = (bid >> 3) & 7;
    int b    = bid >> 6;

    int warp  = threadIdx.x >> 5;
    int lane  = threadIdx.x & 31;
    int rowid = lane & 3;
    int ksub  = lane >> 2;
    int vrow  = vblk * VCHUNK + warp * 4 + rowid;

    float S[16];
#pragma unroll
    for (int i = 0; i < 16; i++) S[i] = 0.f;

    const float* kbase = k + (size_t)(b * TSEQ) * KEYD + h * KDIM + ksub * 16;
    const float* qbase = q + (size_t)(b * TSEQ) * KEYD + h * KDIM + ksub * 16;
    const float* vbase = v + (size_t)(b * TSEQ) * VALD + h * VDIM + vrow;
    const float* abase = alpha + (size_t)(b * TSEQ) * HH + h;
    const float* bbase = beta  + (size_t)(b * TSEQ) * HH + h;
    float* obase = opart + ((size_t)(b * TSEQ) * HH + h) * (8 * VDIM) + ksub * VDIM + vrow;

#define SCAN_LOAD(KT, QT, AV, BV, VV, TT)                                     \
    {                                                                          \
        int tc = (TT) < TSEQ ? (TT) : (TSEQ - 1);                              \
        const float4* kp = (const float4*)(kbase + (size_t)tc * KEYD);         \
        const float4* qp = (const float4*)(qbase + (size_t)tc * KEYD);         \
        ((float4*)(KT))[0] = kp[0]; ((float4*)(KT))[1] = kp[1];                \
        ((float4*)(KT))[2] = kp[2]; ((float4*)(KT))[3] = kp[3];                \
        ((float4*)(QT))[0] = qp[0]; ((float4*)(QT))[1] = qp[1];                \
        ((float4*)(QT))[2] = qp[2]; ((float4*)(QT))[3] = qp[3];                \
        AV = abase[(size_t)tc * HH];                                           \
        BV = bbase[(size_t)tc * HH];                                           \
        VV = vbase[(size_t)tc * VALD];                                         \
    }

#define SCAN_STEP(KT, QT, AV, BV, VV, TT)                                     \
    {                                                                          \
        float r0 = 0.f, r1 = 0.f, r2 = 0.f, r3 = 0.f;                          \
        _Pragma("unroll")                                                      \
        for (int i = 0; i < 4; i++) {                                          \
            r0 = fmaf(S[i],      KT[i],      r0);                              \
            r1 = fmaf(S[i + 4],  KT[i + 4],  r1);                              \
            r2 = fmaf(S[i + 8],  KT[i + 8],  r2);                              \
            r3 = fmaf(S[i + 12], KT[i + 12], r3);                              \
        }                                                                      \
        float r = (r0 + r1) + (r2 + r3);                                       \
        r += __shfl_xor_sync(0xffffffffu, r, 4);                               \
        r += __shfl_xor_sync(0xffffffffu, r, 8);                               \
        r += __shfl_xor_sync(0xffffffffu, r, 16);                              \
        float c1 = BV * VV;                                                    \
        float c2 = AV * BV;                                                    \
        float coef = fmaf(-c2, r, c1);                                         \
        _Pragma("unroll")                                                      \
        for (int i = 0; i < 16; i++)                                           \
            S[i] = fmaf(KT[i], coef, AV * S[i]);                               \
        float o0 = 0.f, o1 = 0.f, o2 = 0.f, o3 = 0.f;                          \
        _Pragma("unroll")                                                      \
        for (int i = 0; i < 4; i++) {                                          \
            o0 = fmaf(S[i],      QT[i],      o0);                              \
            o1 = fmaf(S[i + 4],  QT[i + 4],  o1);                              \
            o2 = fmaf(S[i + 8],  QT[i + 8],  o2);                              \
            o3 = fmaf(S[i + 12], QT[i + 12], o3);                              \
        }                                                                      \
        obase[(size_t)(TT) * (HH * 8 * VDIM)] = (o0 + o1) + (o2 + o3);         \
    }

    float K0[16], Q0[16], a0, b0, v0;
    float K1[16], Q1[16], a1, b1, v1;
    SCAN_LOAD(K0, Q0, a0, b0, v0, 0);
    SCAN_LOAD(K1, Q1, a1, b1, v1, 1);

    for (int t = 0; t < TSEQ; t += 2) {
        SCAN_STEP(K0, Q0, a0, b0, v0, t);
        SCAN_LOAD(K0, Q0, a0, b0, v0, t + 2);
        SCAN_STEP(K1, Q1, a1, b1, v1, t + 1);
        SCAN_LOAD(K1, Q1, a1, b1, v1, t + 3);
    }
#undef SCAN_LOAD
#undef SCAN_STEP
}

// ---------------------------------------------------------------------------
// Sum 8 scan partials + RMS norm + weight + SiLU(gate). One warp per (bt,h).
// lane handles v = i*32 + lane, i in 0..7 (fully coalesced loads).
// ---------------------------------------------------------------------------
__global__ void __launch_bounds__(256) normgate_kernel(
    const float* __restrict__ opart, const float* __restrict__ g,
    const float* __restrict__ w, float* __restrict__ y)
{
    int gw   = (blockIdx.x * 256 + threadIdx.x) >> 5;   // bt*H + h
    int lane = threadIdx.x & 31;
    int bt   = gw >> 3, h = gw & 7;

    const float* pb = opart + (size_t)gw * (8 * VDIM);

    float vals[8];
    float ss = 0.f;
#pragma unroll
    for (int i = 0; i < 8; i++) {
        int vv = i * 32 + lane;
        float s = 0.f;
#pragma unroll
        for (int kk = 0; kk < 8; kk++)
            s += pb[kk * VDIM + vv];
        vals[i] = s;
        ss = fmaf(s, s, ss);
    }
#pragma unroll
    for (int off = 16; off > 0; off >>= 1)
        ss += __shfl_xor_sync(0xffffffffu, ss, off);
    float rms = rsqrtf(ss * (1.f / VDIM) + 1e-5f);

    const float* gp = g + (size_t)bt * PS + h * VDIM;   // g = PROJ + GO
#pragma unroll
    for (int i = 0; i < 8; i++) {
        int vv = i * 32 + lane;
        float gg   = gp[vv];
        float silu = gg / (1.f + expf(-gg));
        y[(size_t)gw * VDIM + vv] = vals[i] * rms * w[vv] * silu;
    }
}

// ---------------------------------------------------------------------------
// Host launcher
// ---------------------------------------------------------------------------
extern "C" void kernel_launch(void* const* d_in, const int* in_sizes, int n_in,
                              void* d_out, int out_size)
{
    const float* x       = (const float*)d_in[0];
    const float* Wq      = (const float*)d_in[1];
    const float* Wk      = (const float*)d_in[2];
    const float* Wv      = (const float*)d_in[3];
    const float* Wa      = (const float*)d_in[4];
    const float* Wb      = (const float*)d_in[5];
    const float* Wg      = (const float*)d_in[6];
    const float* Wo      = (const float*)d_in[7];
    const float* A_log   = (const float*)d_in[8];
    const float* dt_bias = (const float*)d_in[9];
    const float* conv_q  = (const float*)d_in[10];
    const float* conv_k  = (const float*)d_in[11];
    const float* conv_v  = (const float*)d_in[12];
    const float* o_w     = (const float*)d_in[13];
    float* out = (float*)d_out;

    float* arena = nullptr;
    cudaGetSymbolAddress((void**)&arena, g_arena);

    float* wpack = arena + OFF_WPACK;
    float* proj  = arena + OFF_PROJ;
    float* qc    = arena + OFF_QC;
    float* kc    = arena + OFF_KC;
    float* vc    = arena + OFF_VC;
    float* al    = arena + OFF_AL;
    float* be    = arena + OFF_BE;
    float* wabt  = arena + OFF_WABT;
    float* opart = arena + OFF_OPART;
    float* yn    = arena + OFF_YN;

    dim3 blk(256);

    // pack weights
    pack_w_kernel<<<(DD * PS) / 256, blk>>>(Wq, Wk, Wv, Wg, wpack);
    pack_ab_kernel<<<(2 * HH * DD) / 256, blk>>>(Wa, Wb, wabt);

    // fused q|k|v|g projection (TF32 tensor cores), N = 6144
    tf32gemm_kernel<<<dim3(PS / 128, NTOK / 128), blk>>>(x, wpack, proj, NTOK, PS, DD);

    // alpha/beta
    ab_kernel<<<NTOK, blk>>>(x, wabt, A_log, dt_bias, al, be);

    // conv + silu (+ l2norm for q/k)
    conv_silu_l2_kernel<<<(NTOK * HH) / 8, blk>>>(proj + QO, conv_q, qc);
    conv_silu_l2_kernel<<<(NTOK * HH) / 8, blk>>>(proj + KO, conv_k, kc);
    conv_silu_kernel<<<(NTOK * VALD) / 256, blk>>>(proj + VO, conv_v, vc);

    // recurrent scan -> per-ksub partials
    scan_kernel<<<BB * HH * (VDIM / VCHUNK), blk>>>(qc, kc, vc, al, be, opart);

    // partial-sum + rms norm + gate
    normgate_kernel<<<(NTOK * HH) / 8, blk>>>(opart, proj + GO, o_w, yn);

    // output projection
    tf32gemm_kernel<<<dim3(DD / 128, NTOK / 128), blk>>>(yn, Wo, out, NTOK, DD, VALD);
}

// round 9
// speedup vs baseline: 2.4063x; 1.0484x over previous
#include <cuda_runtime.h>
#include <math.h>
#include <stdint.h>

// ---------------------------------------------------------------------------
// Problem constants
// ---------------------------------------------------------------------------
#define BB    2
#define TSEQ  2048
#define DD    1024
#define HH    8
#define KDIM  128
#define VDIM  256
#define KEYD  1024          // H*KDIM
#define VALD  2048          // H*VDIM
#define NTOK  (BB*TSEQ)     // 4096
#define KS    4
#define PS    6144          // packed projection row stride (q|k|v|g)
#define QO    0
#define KO    1024
#define VO    2048
#define GO    4096

// ---------------------------------------------------------------------------
// Scratch arena (device global — no allocation allowed)
// ---------------------------------------------------------------------------
static constexpr size_t OFF_WPACK = 0;                                  // [1024][6144] tf32-rounded
static constexpr size_t OFF_XR    = OFF_WPACK + (size_t)DD * PS;        // [4096][1024] tf32-rounded x
static constexpr size_t OFF_WOR   = OFF_XR    + (size_t)NTOK * DD;      // [2048][1024] tf32-rounded Wo
static constexpr size_t OFF_WABT  = OFF_WOR   + (size_t)VALD * DD;      // [2][8][1024]
static constexpr size_t OFF_PROJ  = OFF_WABT  + (size_t)2 * HH * DD;    // [4096][6144]
static constexpr size_t OFF_QC    = OFF_PROJ  + (size_t)NTOK * PS;      // [4096][1024]
static constexpr size_t OFF_KC    = OFF_QC    + (size_t)NTOK * KEYD;
static constexpr size_t OFF_VC    = OFF_KC    + (size_t)NTOK * KEYD;    // [4096][2048]
static constexpr size_t OFF_AL    = OFF_VC    + (size_t)NTOK * VALD;
static constexpr size_t OFF_BE    = OFF_AL    + (size_t)NTOK * HH;
static constexpr size_t OFF_OPRE  = OFF_BE    + (size_t)NTOK * HH;      // [4096][2048]
static constexpr size_t OFF_YN    = OFF_OPRE  + (size_t)NTOK * VALD;    // [4096][2048] tf32-rounded
static constexpr size_t ARENA_F   = OFF_YN    + (size_t)NTOK * VALD;

__device__ float g_arena[ARENA_F];

// ---------------------------------------------------------------------------
// TF32 helpers
// ---------------------------------------------------------------------------
__device__ __forceinline__ uint32_t f2tf32(float x) {
    uint32_t r;
    asm("cvt.rna.tf32.f32 %0, %1;" : "=r"(r) : "f"(x));
    return r;
}
__device__ __forceinline__ float tf32round(float x) {
    return __uint_as_float(f2tf32(x));
}

__device__ __forceinline__ void mma_tf32(float* c, const uint32_t* a, const uint32_t* b) {
    asm volatile(
        "mma.sync.aligned.m16n8k8.row.col.f32.tf32.tf32.f32 "
        "{%0,%1,%2,%3}, {%4,%5,%6,%7}, {%8,%9}, {%0,%1,%2,%3};"
        : "+f"(c[0]), "+f"(c[1]), "+f"(c[2]), "+f"(c[3])
        : "r"(a[0]), "r"(a[1]), "r"(a[2]), "r"(a[3]), "r"(b[0]), "r"(b[1]));
}

__device__ __forceinline__ void cp16(uint32_t smem_dst, const void* gsrc) {
    asm volatile("cp.async.cg.shared.global [%0], [%1], 16;" :: "r"(smem_dst), "l"(gsrc));
}

// ---------------------------------------------------------------------------
// TF32 tensor-core GEMM on PRE-ROUNDED operands (no cvt in mainloop).
// C[M,N] = A[M,K] @ B[K,N], row-major fp32 containers holding tf32 values.
// BM=128, BN=128, BK=16, 256 threads (8 warps 2x4), warp tile 64x32,
// double-buffered cp.async. M,N,K multiples of 128.
// ---------------------------------------------------------------------------
#define GA_STRIDE 20
#define GB_STRIDE 136

__global__ void __launch_bounds__(256) tf32gemm_kernel(
    const float* __restrict__ A, const float* __restrict__ B,
    float* __restrict__ C, int M, int N, int K)
{
    __shared__ float As[2][128 * GA_STRIDE];
    __shared__ float Bs[2][16 * GB_STRIDE];

    const int tid  = threadIdx.x;
    const int bm   = blockIdx.y, bn = blockIdx.x;
    const int warp = tid >> 5, lane = tid & 31;
    const int wm   = (warp >> 2) * 64;
    const int wn   = (warp & 3) * 32;
    const int gid  = lane >> 2;
    const int tg   = lane & 3;

    const int a_r0 = tid >> 2;
    const int a_c  = (tid & 3) * 4;
    const int b_r0 = tid >> 5;
    const int b_c  = (tid & 31) * 4;

    const float* Ag = A + (size_t)(bm * 128) * K;
    const float* Bg = B + (size_t)bn * 128;

    uint32_t as_base = (uint32_t)__cvta_generic_to_shared(&As[0][0]);
    uint32_t bs_base = (uint32_t)__cvta_generic_to_shared(&Bs[0][0]);
    const uint32_t as_buf = 128 * GA_STRIDE * 4;
    const uint32_t bs_buf = 16 * GB_STRIDE * 4;

    float acc[4][4][4];
#pragma unroll
    for (int i = 0; i < 4; i++)
#pragma unroll
        for (int j = 0; j < 4; j++)
#pragma unroll
            for (int r = 0; r < 4; r++) acc[i][j][r] = 0.f;

    const int niter = K >> 4;

    {
#pragma unroll
        for (int f = 0; f < 2; f++) {
            int row = f * 64 + a_r0;
            cp16(as_base + (uint32_t)((row * GA_STRIDE + a_c) << 2),
                 Ag + (size_t)row * K + a_c);
        }
#pragma unroll
        for (int f = 0; f < 2; f++) {
            int row = f * 8 + b_r0;
            cp16(bs_base + (uint32_t)((row * GB_STRIDE + b_c) << 2),
                 Bg + (size_t)row * N + b_c);
        }
        asm volatile("cp.async.commit_group;");
    }

    for (int it = 0; it < niter; it++) {
        const int p = it & 1;

        if (it + 1 < niter) {
            const int k0 = (it + 1) << 4;
            const uint32_t ao = as_base + (p ^ 1) * as_buf;
            const uint32_t bo = bs_base + (p ^ 1) * bs_buf;
#pragma unroll
            for (int f = 0; f < 2; f++) {
                int row = f * 64 + a_r0;
                cp16(ao + (uint32_t)((row * GA_STRIDE + a_c) << 2),
                     Ag + (size_t)row * K + k0 + a_c);
            }
#pragma unroll
            for (int f = 0; f < 2; f++) {
                int row = f * 8 + b_r0;
                cp16(bo + (uint32_t)((row * GB_STRIDE + b_c) << 2),
                     Bg + (size_t)(k0 + row) * N + b_c);
            }
            asm volatile("cp.async.commit_group;");
            asm volatile("cp.async.wait_group 1;");
        } else {
            asm volatile("cp.async.wait_group 0;");
        }
        __syncthreads();

        const float* Ap = As[p];
        const float* Bp = Bs[p];

#pragma unroll
        for (int ks = 0; ks < 2; ks++) {
            uint32_t af[4][4];
#pragma unroll
            for (int mt = 0; mt < 4; mt++) {
                int r = wm + mt * 16 + gid;
                int c = ks * 8 + tg;
                af[mt][0] = __float_as_uint(Ap[r * GA_STRIDE + c]);
                af[mt][1] = __float_as_uint(Ap[(r + 8) * GA_STRIDE + c]);
                af[mt][2] = __float_as_uint(Ap[r * GA_STRIDE + c + 4]);
                af[mt][3] = __float_as_uint(Ap[(r + 8) * GA_STRIDE + c + 4]);
            }
            uint32_t bf[4][2];
#pragma unroll
            for (int nt = 0; nt < 4; nt++) {
                int n = wn + nt * 8 + gid;
                bf[nt][0] = __float_as_uint(Bp[(ks * 8 + tg) * GB_STRIDE + n]);
                bf[nt][1] = __float_as_uint(Bp[(ks * 8 + 4 + tg) * GB_STRIDE + n]);
            }
#pragma unroll
            for (int mt = 0; mt < 4; mt++)
#pragma unroll
                for (int nt = 0; nt < 4; nt++)
                    mma_tf32(acc[mt][nt], af[mt], bf[nt]);
        }
        __syncthreads();
    }

#pragma unroll
    for (int mt = 0; mt < 4; mt++) {
        int r0 = bm * 128 + wm + mt * 16 + gid;
#pragma unroll
        for (int nt = 0; nt < 4; nt++) {
            int c0 = bn * 128 + wn + nt * 8 + tg * 2;
            *(float2*)(C + (size_t)r0 * N + c0)       = make_float2(acc[mt][nt][0], acc[mt][nt][1]);
            *(float2*)(C + (size_t)(r0 + 8) * N + c0) = make_float2(acc[mt][nt][2], acc[mt][nt][3]);
        }
    }
}

// ---------------------------------------------------------------------------
// Prep kernel (launch 1): pack + tf32-round all GEMM operands, transpose Wab.
// Region map over blockIdx.x (256 thr/blk):
//   [0, 24576)         wpack = tf32(Wq|Wk|Wv|Wg)
//   [24576, 24640)     wabt transpose
//   [24640, 41024)     xr = tf32(x)
//   [41024, 49216)     wor = tf32(Wo)
// ---------------------------------------------------------------------------
#define NB_WPACK 24576
#define NB_AB    64
#define NB_XR    16384
#define NB_WOR   8192

__global__ void __launch_bounds__(256) prep_kernel(
    const float* __restrict__ Wq, const float* __restrict__ Wk,
    const float* __restrict__ Wv, const float* __restrict__ Wg,
    const float* __restrict__ Wa, const float* __restrict__ Wb,
    const float* __restrict__ Wo, const float* __restrict__ x,
    float* __restrict__ wpack, float* __restrict__ wabt,
    float* __restrict__ xr, float* __restrict__ wor)
{
    int bid = blockIdx.x;
    if (bid < NB_WPACK) {
        int idx = bid * 256 + threadIdx.x;
        int col = idx % PS, k = idx / PS;
        float v;
        if (col < 1024)      v = Wq[k * 1024 + col];
        else if (col < 2048) v = Wk[k * 1024 + col - 1024];
        else if (col < 4096) v = Wv[k * 2048 + col - 2048];
        else                 v = Wg[k * 2048 + col - 4096];
        wpack[idx] = tf32round(v);
    } else if (bid < NB_WPACK + NB_AB) {
        int idx = (bid - NB_WPACK) * 256 + threadIdx.x;   // 0..16383
        int k = idx & 1023, h = (idx >> 10) & 7, a = idx >> 13;
        wabt[idx] = a ? Wb[k * 8 + h] : Wa[k * 8 + h];
    } else if (bid < NB_WPACK + NB_AB + NB_XR) {
        int idx = (bid - NB_WPACK - NB_AB) * 256 + threadIdx.x;
        xr[idx] = tf32round(x[idx]);
    } else {
        int idx = (bid - NB_WPACK - NB_AB - NB_XR) * 256 + threadIdx.x;
        wor[idx] = tf32round(Wo[idx]);
    }
}

// ---------------------------------------------------------------------------
// Fused elementwise kernel (launch 3): ab + conv_q + conv_k + conv_v.
// Region map over blockIdx.x:
//   [0, 4096)       ab (token per block)
//   [4096, 8192)    conv+silu+l2 for q
//   [8192, 12288)   conv+silu+l2 for k
//   [12288, 45056)  conv+silu for v
// ---------------------------------------------------------------------------
#define FB_AB   4096
#define FB_CQ   4096
#define FB_CK   4096
#define FB_CV   32768

__device__ __forceinline__ void do_conv_l2(
    const float* __restrict__ in, const float* __restrict__ w,
    float* __restrict__ out, int local_blk)
{
    int gw   = ((local_blk * 256) + (int)threadIdx.x) >> 5;
    int lane = threadIdx.x & 31;
    int h    = gw % HH;
    int bt   = gw / HH;
    int t    = bt % TSEQ;
    int b    = bt / TSEQ;

    int cbase = h * KDIM + lane * 4;

    float acc[4] = {0.f, 0.f, 0.f, 0.f};
    float wt[4][KS];
#pragma unroll
    for (int c = 0; c < 4; c++)
#pragma unroll
        for (int j = 0; j < KS; j++)
            wt[c][j] = w[(cbase + c) * KS + j];

#pragma unroll
    for (int j = 0; j < KS; j++) {
        int tt = t + j - (KS - 1);
        if (tt >= 0) {
            float4 xv = *(const float4*)(in + ((size_t)(b * TSEQ + tt)) * PS + cbase);
#pragma unroll
            for (int c = 0; c < 4; c++)
                acc[c] = fmaf(wt[c][j], (&xv.x)[c], acc[c]);
        }
    }

    float ss = 0.f;
#pragma unroll
    for (int c = 0; c < 4; c++) {
        acc[c] = acc[c] / (1.f + expf(-acc[c]));
        ss = fmaf(acc[c], acc[c], ss);
    }
#pragma unroll
    for (int off = 16; off > 0; off >>= 1)
        ss += __shfl_xor_sync(0xffffffffu, ss, off);
    float s = 1.f / fmaxf(sqrtf(ss), 1e-6f);

    float4 o;
#pragma unroll
    for (int c = 0; c < 4; c++) (&o.x)[c] = acc[c] * s;
    *(float4*)(out + (size_t)bt * KEYD + cbase) = o;
}

__global__ void __launch_bounds__(256) fused_pre_kernel(
    const float* __restrict__ x, const float* __restrict__ proj,
    const float* __restrict__ wabt,
    const float* __restrict__ A_log, const float* __restrict__ dt_bias,
    const float* __restrict__ conv_q, const float* __restrict__ conv_k,
    const float* __restrict__ conv_v,
    float* __restrict__ al, float* __restrict__ be,
    float* __restrict__ qc, float* __restrict__ kc, float* __restrict__ vc)
{
    __shared__ float xs[DD];
    int bid = blockIdx.x;

    if (bid < FB_AB) {
        int t = bid;
        for (int i = threadIdx.x; i < DD; i += 256)
            xs[i] = x[(size_t)t * DD + i];
        __syncthreads();

        int warp = threadIdx.x >> 5;
        int lane = threadIdx.x & 31;
        const float* wa = wabt + warp * 1024;
        const float* wb = wabt + 8192 + warp * 1024;

        float sa = 0.f, sb = 0.f;
#pragma unroll 4
        for (int kk = lane; kk < DD; kk += 32) {
            float xv = xs[kk];
            sa = fmaf(xv, wa[kk], sa);
            sb = fmaf(xv, wb[kk], sb);
        }
#pragma unroll
        for (int off = 16; off > 0; off >>= 1) {
            sa += __shfl_xor_sync(0xffffffffu, sa, off);
            sb += __shfl_xor_sync(0xffffffffu, sb, off);
        }
        if (lane == 0) {
            float z  = sa + dt_bias[warp];
            float sp = (z > 20.f) ? z : log1pf(expf(z));
            al[t * HH + warp] = expf(-expf(A_log[warp]) * sp);
            be[t * HH + warp] = 2.f / (1.f + expf(-sb));
        }
    } else if (bid < FB_AB + FB_CQ) {
        do_conv_l2(proj + QO, conv_q, qc, bid - FB_AB);
    } else if (bid < FB_AB + FB_CQ + FB_CK) {
        do_conv_l2(proj + KO, conv_k, kc, bid - FB_AB - FB_CQ);
    } else {
        int idx = (bid - FB_AB - FB_CQ - FB_CK) * 256 + threadIdx.x;  // NTOK*VALD
        int c  = idx % VALD;
        int bt = idx / VALD;
        int t  = bt % TSEQ;
        int b  = bt / TSEQ;

        float acc = 0.f;
#pragma unroll
        for (int j = 0; j < KS; j++) {
            int tt = t + j - (KS - 1);
            if (tt >= 0)
                acc = fmaf(conv_v[c * KS + j],
                           proj[VO + ((size_t)(b * TSEQ + tt)) * PS + c], acc);
        }
        vc[idx] = acc / (1.f + expf(-acc));
    }
}

// ---------------------------------------------------------------------------
// Recurrent delta-rule scan (launch 4 — gets profiled).
// State in registers; 128 CTAs x 256 threads. Warp: 4 v-rows,
// lane = ksub*4 + rowid; ksub owns 16 k's. Output reduced via 3 shfls
// (off the recurrence critical path), single store at ksub==0.
// Distance-2 register prefetch of q/k/v/alpha/beta.
// ---------------------------------------------------------------------------
#define VCHUNK 32

__global__ void __launch_bounds__(256) scan_kernel(
    const float* __restrict__ q, const float* __restrict__ k,
    const float* __restrict__ v, const float* __restrict__ alpha,
    const float* __restrict__ beta, float* __restrict__ o)
{
    int bid  = blockIdx.x;
    int vblk = bid & 7;
    int h    = (bid >> 3) & 7;
    int b    = bid >> 6;

    int warp  = threadIdx.x >> 5;
    int lane  = threadIdx.x & 31;
    int rowid = lane & 3;
    int ksub  = lane >> 2;
    int vrow  = vblk * VCHUNK + warp * 4 + rowid;

    float S[16];
#pragma unroll
    for (int i = 0; i < 16; i++) S[i] = 0.f;

    const float* kbase = k + (size_t)(b * TSEQ) * KEYD + h * KDIM + ksub * 16;
    const float* qbase = q + (size_t)(b * TSEQ) * KEYD + h * KDIM + ksub * 16;
    const float* vbase = v + (size_t)(b * TSEQ) * VALD + h * VDIM + vrow;
    const float* abase = alpha + (size_t)(b * TSEQ) * HH + h;
    const float* bbase = beta  + (size_t)(b * TSEQ) * HH + h;
    float*       obase = o + (size_t)(b * TSEQ) * VALD + h * VDIM + vrow;

#define SCAN_LOAD(KT, QT, AV, BV, VV, TT)                                     \
    {                                                                          \
        int tc = (TT) < TSEQ ? (TT) : (TSEQ - 1);                              \
        const float4* kp = (const float4*)(kbase + (size_t)tc * KEYD);         \
        const float4* qp = (const float4*)(qbase + (size_t)tc * KEYD);         \
        ((float4*)(KT))[0] = kp[0]; ((float4*)(KT))[1] = kp[1];                \
        ((float4*)(KT))[2] = kp[2]; ((float4*)(KT))[3] = kp[3];                \
        ((float4*)(QT))[0] = qp[0]; ((float4*)(QT))[1] = qp[1];                \
        ((float4*)(QT))[2] = qp[2]; ((float4*)(QT))[3] = qp[3];                \
        AV = abase[(size_t)tc * HH];                                           \
        BV = bbase[(size_t)tc * HH];                                           \
        VV = vbase[(size_t)tc * VALD];                                         \
    }

#define SCAN_STEP(KT, QT, AV, BV, VV, TT)                                     \
    {                                                                          \
        float r0 = 0.f, r1 = 0.f, r2 = 0.f, r3 = 0.f;                          \
        _Pragma("unroll")                                                      \
        for (int i = 0; i < 4; i++) {                                          \
            r0 = fmaf(S[i],      KT[i],      r0);                              \
            r1 = fmaf(S[i + 4],  KT[i + 4],  r1);                              \
            r2 = fmaf(S[i + 8],  KT[i + 8],  r2);                              \
            r3 = fmaf(S[i + 12], KT[i + 12], r3);                              \
        }                                                                      \
        float r = (r0 + r1) + (r2 + r3);                                       \
        r += __shfl_xor_sync(0xffffffffu, r, 4);                               \
        r += __shfl_xor_sync(0xffffffffu, r, 8);                               \
        r += __shfl_xor_sync(0xffffffffu, r, 16);                              \
        float c1 = BV * VV;                                                    \
        float c2 = AV * BV;                                                    \
        float coef = fmaf(-c2, r, c1);                                         \
        _Pragma("unroll")                                                      \
        for (int i = 0; i < 16; i++)                                           \
            S[i] = fmaf(KT[i], coef, AV * S[i]);                               \
        float o0 = 0.f, o1 = 0.f, o2 = 0.f, o3 = 0.f;                          \
        _Pragma("unroll")                                                      \
        for (int i = 0; i < 4; i++) {                                          \
            o0 = fmaf(S[i],      QT[i],      o0);                              \
            o1 = fmaf(S[i + 4],  QT[i + 4],  o1);                              \
            o2 = fmaf(S[i + 8],  QT[i + 8],  o2);                              \
            o3 = fmaf(S[i + 12], QT[i + 12], o3);                              \
        }                                                                      \
        float ov = (o0 + o1) + (o2 + o3);                                      \
        ov += __shfl_xor_sync(0xffffffffu, ov, 4);                             \
        ov += __shfl_xor_sync(0xffffffffu, ov, 8);                             \
        ov += __shfl_xor_sync(0xffffffffu, ov, 16);                            \
        if (ksub == 0) obase[(size_t)(TT) * VALD] = ov;                        \
    }

    float K0[16], Q0[16], a0, b0, v0;
    float K1[16], Q1[16], a1, b1, v1;
    SCAN_LOAD(K0, Q0, a0, b0, v0, 0);
    SCAN_LOAD(K1, Q1, a1, b1, v1, 1);

    for (int t = 0; t < TSEQ; t += 2) {
        SCAN_STEP(K0, Q0, a0, b0, v0, t);
        SCAN_LOAD(K0, Q0, a0, b0, v0, t + 2);
        SCAN_STEP(K1, Q1, a1, b1, v1, t + 1);
        SCAN_LOAD(K1, Q1, a1, b1, v1, t + 3);
    }
#undef SCAN_LOAD
#undef SCAN_STEP
}

// ---------------------------------------------------------------------------
// RMS norm + weight + SiLU(gate), tf32-rounded output. One warp per (bt,h).
// ---------------------------------------------------------------------------
__global__ void __launch_bounds__(256) normgate_kernel(
    const float* __restrict__ o, const float* __restrict__ proj,
    const float* __restrict__ w, float* __restrict__ y)
{
    int gw   = (blockIdx.x * 256 + threadIdx.x) >> 5;   // bt*H + h
    int lane = threadIdx.x & 31;
    int bt   = gw >> 3, h = gw & 7;

    const float* op = o + (size_t)gw * VDIM + lane * 8;
    const float* gp = proj + GO + (size_t)bt * PS + h * VDIM + lane * 8;
    float*       yp = y + (size_t)gw * VDIM + lane * 8;

    float vals[8];
    *(float4*)(vals)     = *(const float4*)(op);
    *(float4*)(vals + 4) = *(const float4*)(op + 4);

    float ss = 0.f;
#pragma unroll
    for (int i = 0; i < 8; i++) ss = fmaf(vals[i], vals[i], ss);
#pragma unroll
    for (int off = 16; off > 0; off >>= 1)
        ss += __shfl_xor_sync(0xffffffffu, ss, off);
    float rms = rsqrtf(ss * (1.f / VDIM) + 1e-5f);

    float gv[8];
    *(float4*)(gv)     = *(const float4*)(gp);
    *(float4*)(gv + 4) = *(const float4*)(gp + 4);

    float out[8];
#pragma unroll
    for (int i = 0; i < 8; i++) {
        float gg   = gv[i];
        float silu = gg / (1.f + expf(-gg));
        out[i] = tf32round(vals[i] * rms * w[lane * 8 + i] * silu);
    }
    *(float4*)(yp)     = *(float4*)(out);
    *(float4*)(yp + 4) = *(float4*)(out + 4);
}

// ---------------------------------------------------------------------------
// Host launcher
// ---------------------------------------------------------------------------
extern "C" void kernel_launch(void* const* d_in, const int* in_sizes, int n_in,
                              void* d_out, int out_size)
{
    const float* x       = (const float*)d_in[0];
    const float* Wq      = (const float*)d_in[1];
    const float* Wk      = (const float*)d_in[2];
    const float* Wv      = (const float*)d_in[3];
    const float* Wa      = (const float*)d_in[4];
    const float* Wb      = (const float*)d_in[5];
    const float* Wg      = (const float*)d_in[6];
    const float* Wo      = (const float*)d_in[7];
    const float* A_log   = (const float*)d_in[8];
    const float* dt_bias = (const float*)d_in[9];
    const float* conv_q  = (const float*)d_in[10];
    const float* conv_k  = (const float*)d_in[11];
    const float* conv_v  = (const float*)d_in[12];
    const float* o_w     = (const float*)d_in[13];
    float* out = (float*)d_out;

    float* arena = nullptr;
    cudaGetSymbolAddress((void**)&arena, g_arena);

    float* wpack = arena + OFF_WPACK;
    float* xr    = arena + OFF_XR;
    float* wor   = arena + OFF_WOR;
    float* wabt  = arena + OFF_WABT;
    float* proj  = arena + OFF_PROJ;
    float* qc    = arena + OFF_QC;
    float* kc    = arena + OFF_KC;
    float* vc    = arena + OFF_VC;
    float* al    = arena + OFF_AL;
    float* be    = arena + OFF_BE;
    float* opre  = arena + OFF_OPRE;
    float* yn    = arena + OFF_YN;

    dim3 blk(256);

    // 1. pack + tf32-round all GEMM operands
    prep_kernel<<<NB_WPACK + NB_AB + NB_XR + NB_WOR, blk>>>(
        Wq, Wk, Wv, Wg, Wa, Wb, Wo, x, wpack, wabt, xr, wor);

    // 2. fused q|k|v|g projection (pre-rounded TF32)
    tf32gemm_kernel<<<dim3(PS / 128, NTOK / 128), blk>>>(xr, wpack, proj, NTOK, PS, DD);

    // 3. fused alpha/beta + convs
    fused_pre_kernel<<<FB_AB + FB_CQ + FB_CK + FB_CV, blk>>>(
        x, proj, wabt, A_log, dt_bias, conv_q, conv_k, conv_v,
        al, be, qc, kc, vc);

    // 4. recurrent scan (profiled slot)
    scan_kernel<<<BB * HH * (VDIM / VCHUNK), blk>>>(qc, kc, vc, al, be, opre);

    // 5. rms norm + gate (tf32-rounded output)
    normgate_kernel<<<(NTOK * HH) / 8, blk>>>(opre, proj, o_w, yn);

    // 6. output projection (pre-rounded TF32)
    tf32gemm_kernel<<<dim3(DD / 128, NTOK / 128), blk>>>(yn, wor, out, NTOK, DD, VALD);
}

// round 10
// speedup vs baseline: 2.5982x; 1.0797x over previous
#include <cuda_runtime.h>
#include <math.h>
#include <stdint.h>

// ---------------------------------------------------------------------------
// Problem constants
// ---------------------------------------------------------------------------
#define BB    2
#define TSEQ  2048
#define DD    1024
#define HH    8
#define KDIM  128
#define VDIM  256
#define KEYD  1024          // H*KDIM
#define VALD  2048          // H*VDIM
#define NTOK  (BB*TSEQ)     // 4096
#define KS    4
#define PS    6144          // packed projection row stride (q|k|v|g)
#define QO    0
#define KO    1024
#define VO    2048
#define GO    4096

// ---------------------------------------------------------------------------
// Scratch arena (device global — no allocation allowed)
// ---------------------------------------------------------------------------
static constexpr size_t OFF_WPACK = 0;                                  // [1024][6144] tf32-rounded
static constexpr size_t OFF_XR    = OFF_WPACK + (size_t)DD * PS;        // [4096][1024] tf32-rounded x
static constexpr size_t OFF_WOR   = OFF_XR    + (size_t)NTOK * DD;      // [2048][1024] tf32-rounded Wo
static constexpr size_t OFF_WABT  = OFF_WOR   + (size_t)VALD * DD;      // [2][8][1024]
static constexpr size_t OFF_PROJ  = OFF_WABT  + (size_t)2 * HH * DD;    // [4096][6144]
static constexpr size_t OFF_QC    = OFF_PROJ  + (size_t)NTOK * PS;      // [4096][1024]
static constexpr size_t OFF_KC    = OFF_QC    + (size_t)NTOK * KEYD;
static constexpr size_t OFF_VC    = OFF_KC    + (size_t)NTOK * KEYD;    // [4096][2048]
static constexpr size_t OFF_ABCD  = OFF_VC    + (size_t)NTOK * VALD;    // [NTOK*HH][4] = alpha,beta,c,d
static constexpr size_t OFF_OPRE  = OFF_ABCD  + (size_t)NTOK * HH * 4;  // [4096][2048]
static constexpr size_t OFF_YN    = OFF_OPRE  + (size_t)NTOK * VALD;    // [4096][2048] tf32-rounded
static constexpr size_t ARENA_F   = OFF_YN    + (size_t)NTOK * VALD;

__device__ float g_arena[ARENA_F];

// ---------------------------------------------------------------------------
// TF32 helpers
// ---------------------------------------------------------------------------
__device__ __forceinline__ uint32_t f2tf32(float x) {
    uint32_t r;
    asm("cvt.rna.tf32.f32 %0, %1;" : "=r"(r) : "f"(x));
    return r;
}
__device__ __forceinline__ float tf32round(float x) {
    return __uint_as_float(f2tf32(x));
}

__device__ __forceinline__ void mma_tf32(float* c, const uint32_t* a, const uint32_t* b) {
    asm volatile(
        "mma.sync.aligned.m16n8k8.row.col.f32.tf32.tf32.f32 "
        "{%0,%1,%2,%3}, {%4,%5,%6,%7}, {%8,%9}, {%0,%1,%2,%3};"
        : "+f"(c[0]), "+f"(c[1]), "+f"(c[2]), "+f"(c[3])
        : "r"(a[0]), "r"(a[1]), "r"(a[2]), "r"(a[3]), "r"(b[0]), "r"(b[1]));
}

__device__ __forceinline__ void cp16(uint32_t smem_dst, const void* gsrc) {
    asm volatile("cp.async.cg.shared.global [%0], [%1], 16;" :: "r"(smem_dst), "l"(gsrc));
}

// ---------------------------------------------------------------------------
// TF32 tensor-core GEMM on PRE-ROUNDED operands (no cvt in mainloop).
// C[M,N] = A[M,K] @ B[K,N], row-major fp32 containers holding tf32 values.
// BM=128, BN=128, BK=16, 256 threads (8 warps 2x4), warp tile 64x32,
// double-buffered cp.async. M,N,K multiples of 128.
// ---------------------------------------------------------------------------
#define GA_STRIDE 20
#define GB_STRIDE 136

__global__ void __launch_bounds__(256) tf32gemm_kernel(
    const float* __restrict__ A, const float* __restrict__ B,
    float* __restrict__ C, int M, int N, int K)
{
    __shared__ float As[2][128 * GA_STRIDE];
    __shared__ float Bs[2][16 * GB_STRIDE];

    const int tid  = threadIdx.x;
    const int bm   = blockIdx.y, bn = blockIdx.x;
    const int warp = tid >> 5, lane = tid & 31;
    const int wm   = (warp >> 2) * 64;
    const int wn   = (warp & 3) * 32;
    const int gid  = lane >> 2;
    const int tg   = lane & 3;

    const int a_r0 = tid >> 2;
    const int a_c  = (tid & 3) * 4;
    const int b_r0 = tid >> 5;
    const int b_c  = (tid & 31) * 4;

    const float* Ag = A + (size_t)(bm * 128) * K;
    const float* Bg = B + (size_t)bn * 128;

    uint32_t as_base = (uint32_t)__cvta_generic_to_shared(&As[0][0]);
    uint32_t bs_base = (uint32_t)__cvta_generic_to_shared(&Bs[0][0]);
    const uint32_t as_buf = 128 * GA_STRIDE * 4;
    const uint32_t bs_buf = 16 * GB_STRIDE * 4;

    float acc[4][4][4];
#pragma unroll
    for (int i = 0; i < 4; i++)
#pragma unroll
        for (int j = 0; j < 4; j++)
#pragma unroll
            for (int r = 0; r < 4; r++) acc[i][j][r] = 0.f;

    const int niter = K >> 4;

    {
#pragma unroll
        for (int f = 0; f < 2; f++) {
            int row = f * 64 + a_r0;
            cp16(as_base + (uint32_t)((row * GA_STRIDE + a_c) << 2),
                 Ag + (size_t)row * K + a_c);
        }
#pragma unroll
        for (int f = 0; f < 2; f++) {
            int row = f * 8 + b_r0;
            cp16(bs_base + (uint32_t)((row * GB_STRIDE + b_c) << 2),
                 Bg + (size_t)row * N + b_c);
        }
        asm volatile("cp.async.commit_group;");
    }

    for (int it = 0; it < niter; it++) {
        const int p = it & 1;

        if (it + 1 < niter) {
            const int k0 = (it + 1) << 4;
            const uint32_t ao = as_base + (p ^ 1) * as_buf;
            const uint32_t bo = bs_base + (p ^ 1) * bs_buf;
#pragma unroll
            for (int f = 0; f < 2; f++) {
                int row = f * 64 + a_r0;
                cp16(ao + (uint32_t)((row * GA_STRIDE + a_c) << 2),
                     Ag + (size_t)row * K + k0 + a_c);
            }
#pragma unroll
            for (int f = 0; f < 2; f++) {
                int row = f * 8 + b_r0;
                cp16(bo + (uint32_t)((row * GB_STRIDE + b_c) << 2),
                     Bg + (size_t)(k0 + row) * N + b_c);
            }
            asm volatile("cp.async.commit_group;");
            asm volatile("cp.async.wait_group 1;");
        } else {
            asm volatile("cp.async.wait_group 0;");
        }
        __syncthreads();

        const float* Ap = As[p];
        const float* Bp = Bs[p];

#pragma unroll
        for (int ks = 0; ks < 2; ks++) {
            uint32_t af[4][4];
#pragma unroll
            for (int mt = 0; mt < 4; mt++) {
                int r = wm + mt * 16 + gid;
                int c = ks * 8 + tg;
                af[mt][0] = __float_as_uint(Ap[r * GA_STRIDE + c]);
                af[mt][1] = __float_as_uint(Ap[(r + 8) * GA_STRIDE + c]);
                af[mt][2] = __float_as_uint(Ap[r * GA_STRIDE + c + 4]);
                af[mt][3] = __float_as_uint(Ap[(r + 8) * GA_STRIDE + c + 4]);
            }
            uint32_t bf[4][2];
#pragma unroll
            for (int nt = 0; nt < 4; nt++) {
                int n = wn + nt * 8 + gid;
                bf[nt][0] = __float_as_uint(Bp[(ks * 8 + tg) * GB_STRIDE + n]);
                bf[nt][1] = __float_as_uint(Bp[(ks * 8 + 4 + tg) * GB_STRIDE + n]);
            }
#pragma unroll
            for (int mt = 0; mt < 4; mt++)
#pragma unroll
                for (int nt = 0; nt < 4; nt++)
                    mma_tf32(acc[mt][nt], af[mt], bf[nt]);
        }
        __syncthreads();
    }

#pragma unroll
    for (int mt = 0; mt < 4; mt++) {
        int r0 = bm * 128 + wm + mt * 16 + gid;
#pragma unroll
        for (int nt = 0; nt < 4; nt++) {
            int c0 = bn * 128 + wn + nt * 8 + tg * 2;
            *(float2*)(C + (size_t)r0 * N + c0)       = make_float2(acc[mt][nt][0], acc[mt][nt][1]);
            *(float2*)(C + (size_t)(r0 + 8) * N + c0) = make_float2(acc[mt][nt][2], acc[mt][nt][3]);
        }
    }
}

// ---------------------------------------------------------------------------
// Prep kernel (launch 1): pack + tf32-round all GEMM operands, transpose Wab.
// ---------------------------------------------------------------------------
#define NB_WPACK 24576
#define NB_AB    64
#define NB_XR    16384
#define NB_WOR   8192

__global__ void __launch_bounds__(256) prep_kernel(
    const float* __restrict__ Wq, const float* __restrict__ Wk,
    const float* __restrict__ Wv, const float* __restrict__ Wg,
    const float* __restrict__ Wa, const float* __restrict__ Wb,
    const float* __restrict__ Wo, const float* __restrict__ x,
    float* __restrict__ wpack, float* __restrict__ wabt,
    float* __restrict__ xr, float* __restrict__ wor)
{
    int bid = blockIdx.x;
    if (bid < NB_WPACK) {
        int idx = bid * 256 + threadIdx.x;
        int col = idx % PS, k = idx / PS;
        float v;
        if (col < 1024)      v = Wq[k * 1024 + col];
        else if (col < 2048) v = Wk[k * 1024 + col - 1024];
        else if (col < 4096) v = Wv[k * 2048 + col - 2048];
        else                 v = Wg[k * 2048 + col - 4096];
        wpack[idx] = tf32round(v);
    } else if (bid < NB_WPACK + NB_AB) {
        int idx = (bid - NB_WPACK) * 256 + threadIdx.x;   // 0..16383
        int k = idx & 1023, h = (idx >> 10) & 7, a = idx >> 13;
        wabt[idx] = a ? Wb[k * 8 + h] : Wa[k * 8 + h];
    } else if (bid < NB_WPACK + NB_AB + NB_XR) {
        int idx = (bid - NB_WPACK - NB_AB) * 256 + threadIdx.x;
        xr[idx] = tf32round(x[idx]);
    } else {
        int idx = (bid - NB_WPACK - NB_AB - NB_XR) * 256 + threadIdx.x;
        wor[idx] = tf32round(Wo[idx]);
    }
}

// ---------------------------------------------------------------------------
// Fused elementwise kernel (launch 3): ab + conv_q + conv_k + conv_v.
// ab region writes alpha,beta into abcd[gw][0..1] (c,d filled by ckd_kernel).
// ---------------------------------------------------------------------------
#define FB_AB   4096
#define FB_CQ   4096
#define FB_CK   4096
#define FB_CV   32768

__device__ __forceinline__ void do_conv_l2(
    const float* __restrict__ in, const float* __restrict__ w,
    float* __restrict__ out, int local_blk)
{
    int gw   = ((local_blk * 256) + (int)threadIdx.x) >> 5;
    int lane = threadIdx.x & 31;
    int h    = gw % HH;
    int bt   = gw / HH;
    int t    = bt % TSEQ;
    int b    = bt / TSEQ;

    int cbase = h * KDIM + lane * 4;

    float acc[4] = {0.f, 0.f, 0.f, 0.f};
    float wt[4][KS];
#pragma unroll
    for (int c = 0; c < 4; c++)
#pragma unroll
        for (int j = 0; j < KS; j++)
            wt[c][j] = w[(cbase + c) * KS + j];

#pragma unroll
    for (int j = 0; j < KS; j++) {
        int tt = t + j - (KS - 1);
        if (tt >= 0) {
            float4 xv = *(const float4*)(in + ((size_t)(b * TSEQ + tt)) * PS + cbase);
#pragma unroll
            for (int c = 0; c < 4; c++)
                acc[c] = fmaf(wt[c][j], (&xv.x)[c], acc[c]);
        }
    }

    float ss = 0.f;
#pragma unroll
    for (int c = 0; c < 4; c++) {
        acc[c] = acc[c] / (1.f + expf(-acc[c]));
        ss = fmaf(acc[c], acc[c], ss);
    }
#pragma unroll
    for (int off = 16; off > 0; off >>= 1)
        ss += __shfl_xor_sync(0xffffffffu, ss, off);
    float s = 1.f / fmaxf(sqrtf(ss), 1e-6f);

    float4 o;
#pragma unroll
    for (int c = 0; c < 4; c++) (&o.x)[c] = acc[c] * s;
    *(float4*)(out + (size_t)bt * KEYD + cbase) = o;
}

__global__ void __launch_bounds__(256) fused_pre_kernel(
    const float* __restrict__ x, const float* __restrict__ proj,
    const float* __restrict__ wabt,
    const float* __restrict__ A_log, const float* __restrict__ dt_bias,
    const float* __restrict__ conv_q, const float* __restrict__ conv_k,
    const float* __restrict__ conv_v,
    float* __restrict__ abcd,
    float* __restrict__ qc, float* __restrict__ kc, float* __restrict__ vc)
{
    __shared__ float xs[DD];
    int bid = blockIdx.x;

    if (bid < FB_AB) {
        int t = bid;
        for (int i = threadIdx.x; i < DD; i += 256)
            xs[i] = x[(size_t)t * DD + i];
        __syncthreads();

        int warp = threadIdx.x >> 5;
        int lane = threadIdx.x & 31;
        const float* wa = wabt + warp * 1024;
        const float* wb = wabt + 8192 + warp * 1024;

        float sa = 0.f, sb = 0.f;
#pragma unroll 4
        for (int kk = lane; kk < DD; kk += 32) {
            float xv = xs[kk];
            sa = fmaf(xv, wa[kk], sa);
            sb = fmaf(xv, wb[kk], sb);
        }
#pragma unroll
        for (int off = 16; off > 0; off >>= 1) {
            sa += __shfl_xor_sync(0xffffffffu, sa, off);
            sb += __shfl_xor_sync(0xffffffffu, sb, off);
        }
        if (lane == 0) {
            float z  = sa + dt_bias[warp];
            float sp = (z > 20.f) ? z : log1pf(expf(z));
            float alpha = expf(-expf(A_log[warp]) * sp);
            float beta  = 2.f / (1.f + expf(-sb));
            *(float2*)(abcd + (size_t)(t * HH + warp) * 4) = make_float2(alpha, beta);
        }
    } else if (bid < FB_AB + FB_CQ) {
        do_conv_l2(proj + QO, conv_q, qc, bid - FB_AB);
    } else if (bid < FB_AB + FB_CQ + FB_CK) {
        do_conv_l2(proj + KO, conv_k, kc, bid - FB_AB - FB_CQ);
    } else {
        int idx = (bid - FB_AB - FB_CQ - FB_CK) * 256 + threadIdx.x;  // NTOK*VALD
        int c  = idx % VALD;
        int bt = idx / VALD;
        int t  = bt % TSEQ;
        int b  = bt / TSEQ;

        float acc = 0.f;
#pragma unroll
        for (int j = 0; j < KS; j++) {
            int tt = t + j - (KS - 1);
            if (tt >= 0)
                acc = fmaf(conv_v[c * KS + j],
                           proj[VO + ((size_t)(b * TSEQ + tt)) * PS + c], acc);
        }
        vc[idx] = acc / (1.f + expf(-acc));
    }
}

// ---------------------------------------------------------------------------
// ckd kernel (launch 4): per (token, head) precompute
//   c_t = k_t . k_{t+1}   (0 at sequence end)
//   d_t = k_t . q_t
// into abcd[gw][2..3]. One warp per (bt, h).
// ---------------------------------------------------------------------------
__global__ void __launch_bounds__(256) ckd_kernel(
    const float* __restrict__ qc, const float* __restrict__ kc,
    float* __restrict__ abcd)
{
    int gw   = (blockIdx.x * 256 + threadIdx.x) >> 5;   // bt*HH + h
    int lane = threadIdx.x & 31;
    int h    = gw & 7;
    int bt   = gw >> 3;
    int t    = bt & (TSEQ - 1);

    const float* kp = kc + (size_t)bt * KEYD + h * KDIM + lane * 4;
    const float* qp = qc + (size_t)bt * KEYD + h * KDIM + lane * 4;
    float4 kt = *(const float4*)kp;
    float4 qt = *(const float4*)qp;
    float4 kn = make_float4(0.f, 0.f, 0.f, 0.f);
    if (t < TSEQ - 1) kn = *(const float4*)(kp + KEYD);

    float c = kt.x * kn.x + kt.y * kn.y + kt.z * kn.z + kt.w * kn.w;
    float d = kt.x * qt.x + kt.y * qt.y + kt.z * qt.z + kt.w * qt.w;
#pragma unroll
    for (int off = 16; off > 0; off >>= 1) {
        c += __shfl_xor_sync(0xffffffffu, c, off);
        d += __shfl_xor_sync(0xffffffffu, d, off);
    }
    if (lane == 0)
        *(float2*)(abcd + (size_t)gw * 4 + 2) = make_float2(c, d);
}

// ---------------------------------------------------------------------------
// Recurrent delta-rule scan with lookahead-1 (launch 5).
// State S[16] in regs; 128 CTAs x 256 threads; lane = ksub*4 + rowid.
// Identities (exact):
//   S_t    = a_t S_{t-1} + coef_t k_t^T,  coef_t = b_t v_t - a_t b_t r_t
//   r_t    = a_{t-1} u_t + coef_{t-1} c_{t-1},  u_t = S_{t-2}.k_t
//   o_t    = a_t w_t + coef_t d_t,              w_t = S_{t-1}.q_t
// c,d precomputed; u,w dots (16 FMA + 3 shfl) have >= 1 iter of slack, so
// the serial chain is only a few scalar FMAs. Depth-4 register ring gives
// 3-iteration load lookahead.
// ---------------------------------------------------------------------------
__global__ void __launch_bounds__(256) scan_kernel(
    const float* __restrict__ q, const float* __restrict__ k,
    const float* __restrict__ v, const float* __restrict__ abcd,
    float* __restrict__ o)
{
    int bid  = blockIdx.x;
    int vblk = bid & 7;
    int h    = (bid >> 3) & 7;
    int b    = bid >> 6;

    int warp  = threadIdx.x >> 5;
    int lane  = threadIdx.x & 31;
    int rowid = lane & 3;
    int ksub  = lane >> 2;
    int vrow  = vblk * 32 + warp * 4 + rowid;

    float S[16];
#pragma unroll
    for (int i = 0; i < 16; i++) S[i] = 0.f;

    const float* kbase = k + (size_t)(b * TSEQ) * KEYD + h * KDIM + ksub * 16;
    const float* qbase = q + (size_t)(b * TSEQ) * KEYD + h * KDIM + ksub * 16;
    const float* vbase = v + (size_t)(b * TSEQ) * VALD + h * VDIM + vrow;
    const float* sbase = abcd + ((size_t)(b * TSEQ) * HH + h) * 4;
    float*       obase = o + (size_t)(b * TSEQ) * VALD + h * VDIM + vrow;

    // ring buffers: slot s (= t%4) holds k_{t+1}, q_t, {a,b,c,d}_t, v_t
    float  KB[4][16], QB[4][16];
    float4 SC[4];
    float  VB[4];
    float  u = 0.f, pa = 0.f, pcoef = 0.f, pcc = 0.f;

#define LOADSLOT(s, TT)                                                        \
    {                                                                          \
        int tc = (TT) < TSEQ ? (TT) : (TSEQ - 1);                              \
        int tk = (TT) + 1 < TSEQ ? (TT) + 1 : (TSEQ - 1);                      \
        const float4* kp = (const float4*)(kbase + (size_t)tk * KEYD);         \
        ((float4*)KB[s])[0] = kp[0]; ((float4*)KB[s])[1] = kp[1];              \
        ((float4*)KB[s])[2] = kp[2]; ((float4*)KB[s])[3] = kp[3];              \
        const float4* qp = (const float4*)(qbase + (size_t)tc * KEYD);         \
        ((float4*)QB[s])[0] = qp[0]; ((float4*)QB[s])[1] = qp[1];              \
        ((float4*)QB[s])[2] = qp[2]; ((float4*)QB[s])[3] = qp[3];              \
        SC[s] = *(const float4*)(sbase + (size_t)tc * (HH * 4));               \
        VB[s] = vbase[(size_t)tc * VALD];                                      \
    }

#define STEP(s, sp, TT)                                                        \
    {                                                                          \
        float aa = SC[s].x, bb = SC[s].y, cc = SC[s].z, dd = SC[s].w;          \
        float vv = VB[s];                                                      \
        float r    = fmaf(pa, u, pcoef * pcc);                                 \
        float coef = fmaf(-(aa * bb), r, bb * vv);                             \
        float u0 = 0.f, u1 = 0.f, u2 = 0.f, u3 = 0.f;                          \
        float w0 = 0.f, w1 = 0.f, w2 = 0.f, w3 = 0.f;                          \
        _Pragma("unroll")                                                      \
        for (int i = 0; i < 4; i++) {                                          \
            u0 = fmaf(S[i],      KB[s][i],      u0);                           \
            u1 = fmaf(S[i + 4],  KB[s][i + 4],  u1);                           \
            u2 = fmaf(S[i + 8],  KB[s][i + 8],  u2);                           \
            u3 = fmaf(S[i + 12], KB[s][i + 12], u3);                           \
            w0 = fmaf(S[i],      QB[s][i],      w0);                           \
            w1 = fmaf(S[i + 4],  QB[s][i + 4],  w1);                           \
            w2 = fmaf(S[i + 8],  QB[s][i + 8],  w2);                           \
            w3 = fmaf(S[i + 12], QB[s][i + 12], w3);                           \
        }                                                                      \
        float un = (u0 + u1) + (u2 + u3);                                      \
        float wn = (w0 + w1) + (w2 + w3);                                      \
        un += __shfl_xor_sync(0xffffffffu, un, 4);                             \
        un += __shfl_xor_sync(0xffffffffu, un, 8);                             \
        un += __shfl_xor_sync(0xffffffffu, un, 16);                            \
        wn += __shfl_xor_sync(0xffffffffu, wn, 4);                             \
        wn += __shfl_xor_sync(0xffffffffu, wn, 8);                             \
        wn += __shfl_xor_sync(0xffffffffu, wn, 16);                            \
        _Pragma("unroll")                                                      \
        for (int i = 0; i < 16; i++)                                           \
            S[i] = fmaf(KB[sp][i], coef, aa * S[i]);                           \
        float ov = fmaf(coef, dd, aa * wn);                                    \
        if (ksub == 0) obase[(size_t)(TT) * VALD] = ov;                        \
        u = un; pa = aa; pcoef = coef; pcc = cc;                               \
    }

    // prologue: slots 0..2 for t = 0..2; slot 3 acts as "time -1" (only its
    // K part, holding k_0, is consumed before the slot is reloaded)
    LOADSLOT(0, 0);
    LOADSLOT(1, 1);
    LOADSLOT(2, 2);
    {
        const float4* kp = (const float4*)(kbase);
        ((float4*)KB[3])[0] = kp[0]; ((float4*)KB[3])[1] = kp[1];
        ((float4*)KB[3])[2] = kp[2]; ((float4*)KB[3])[3] = kp[3];
#pragma unroll
        for (int i = 0; i < 16; i++) QB[3][i] = 0.f;
        SC[3] = make_float4(0.f, 0.f, 0.f, 0.f);
        VB[3] = 0.f;
    }

    for (int t = 0; t < TSEQ; t += 4) {
        STEP(0, 3, t);     LOADSLOT(3, t + 3);
        STEP(1, 0, t + 1); LOADSLOT(0, t + 4);
        STEP(2, 1, t + 2); LOADSLOT(1, t + 5);
        STEP(3, 2, t + 3); LOADSLOT(2, t + 6);
    }
#undef LOADSLOT
#undef STEP
}

// ---------------------------------------------------------------------------
// RMS norm + weight + SiLU(gate), tf32-rounded output. One warp per (bt,h).
// ---------------------------------------------------------------------------
__global__ void __launch_bounds__(256) normgate_kernel(
    const float* __restrict__ o, const float* __restrict__ proj,
    const float* __restrict__ w, float* __restrict__ y)
{
    int gw   = (blockIdx.x * 256 + threadIdx.x) >> 5;   // bt*H + h
    int lane = threadIdx.x & 31;
    int bt   = gw >> 3, h = gw & 7;

    const float* op = o + (size_t)gw * VDIM + lane * 8;
    const float* gp = proj + GO + (size_t)bt * PS + h * VDIM + lane * 8;
    float*       yp = y + (size_t)gw * VDIM + lane * 8;

    float vals[8];
    *(float4*)(vals)     = *(const float4*)(op);
    *(float4*)(vals + 4) = *(const float4*)(op + 4);

    float ss = 0.f;
#pragma unroll
    for (int i = 0; i < 8; i++) ss = fmaf(vals[i], vals[i], ss);
#pragma unroll
    for (int off = 16; off > 0; off >>= 1)
        ss += __shfl_xor_sync(0xffffffffu, ss, off);
    float rms = rsqrtf(ss * (1.f / VDIM) + 1e-5f);

    float gv[8];
    *(float4*)(gv)     = *(const float4*)(gp);
    *(float4*)(gv + 4) = *(const float4*)(gp + 4);

    float out[8];
#pragma unroll
    for (int i = 0; i < 8; i++) {
        float gg   = gv[i];
        float silu = gg / (1.f + expf(-gg));
        out[i] = tf32round(vals[i] * rms * w[lane * 8 + i] * silu);
    }
    *(float4*)(yp)     = *(float4*)(out);
    *(float4*)(yp + 4) = *(float4*)(out + 4);
}

// ---------------------------------------------------------------------------
// Host launcher
// ---------------------------------------------------------------------------
extern "C" void kernel_launch(void* const* d_in, const int* in_sizes, int n_in,
                              void* d_out, int out_size)
{
    const float* x       = (const float*)d_in[0];
    const float* Wq      = (const float*)d_in[1];
    const float* Wk      = (const float*)d_in[2];
    const float* Wv      = (const float*)d_in[3];
    const float* Wa      = (const float*)d_in[4];
    const float* Wb      = (const float*)d_in[5];
    const float* Wg      = (const float*)d_in[6];
    const float* Wo      = (const float*)d_in[7];
    const float* A_log   = (const float*)d_in[8];
    const float* dt_bias = (const float*)d_in[9];
    const float* conv_q  = (const float*)d_in[10];
    const float* conv_k  = (const float*)d_in[11];
    const float* conv_v  = (const float*)d_in[12];
    const float* o_w     = (const float*)d_in[13];
    float* out = (float*)d_out;

    float* arena = nullptr;
    cudaGetSymbolAddress((void**)&arena, g_arena);

    float* wpack = arena + OFF_WPACK;
    float* xr    = arena + OFF_XR;
    float* wor   = arena + OFF_WOR;
    float* wabt  = arena + OFF_WABT;
    float* proj  = arena + OFF_PROJ;
    float* qc    = arena + OFF_QC;
    float* kc    = arena + OFF_KC;
    float* vc    = arena + OFF_VC;
    float* abcd  = arena + OFF_ABCD;
    float* opre  = arena + OFF_OPRE;
    float* yn    = arena + OFF_YN;

    dim3 blk(256);

    // 1. pack + tf32-round all GEMM operands
    prep_kernel<<<NB_WPACK + NB_AB + NB_XR + NB_WOR, blk>>>(
        Wq, Wk, Wv, Wg, Wa, Wb, Wo, x, wpack, wabt, xr, wor);

    // 2. fused q|k|v|g projection (pre-rounded TF32)
    tf32gemm_kernel<<<dim3(PS / 128, NTOK / 128), blk>>>(xr, wpack, proj, NTOK, PS, DD);

    // 3. fused alpha/beta + convs
    fused_pre_kernel<<<FB_AB + FB_CQ + FB_CK + FB_CV, blk>>>(
        x, proj, wabt, A_log, dt_bias, conv_q, conv_k, conv_v,
        abcd, qc, kc, vc);

    // 4. precompute c = k_t.k_{t+1}, d = k_t.q_t
    ckd_kernel<<<(NTOK * HH) / 8, blk>>>(qc, kc, abcd);

    // 5. recurrent scan (lookahead-1, depth-4 prefetch)
    scan_kernel<<<BB * HH * (VDIM / 32), blk>>>(qc, kc, vc, abcd, opre);

    // 6. rms norm + gate (tf32-rounded output)
    normgate_kernel<<<(NTOK * HH) / 8, blk>>>(opre, proj, o_w, yn);

    // 7. output projection (pre-rounded TF32)
    tf32gemm_kernel<<<dim3(DD / 128, NTOK / 128), blk>>>(yn, wor, out, NTOK, DD, VALD);
}

// round 11
// speedup vs baseline: 3.8010x; 1.4629x over previous
#include <cuda_runtime.h>
#include <math.h>
#include <stdint.h>

// ---------------------------------------------------------------------------
// Problem constants
// ---------------------------------------------------------------------------
#define BB    2
#define TSEQ  2048
#define DD    1024
#define HH    8
#define KDIM  128
#define VDIM  256
#define KEYD  1024          // H*KDIM
#define VALD  2048          // H*VDIM
#define NTOK  (BB*TSEQ)     // 4096
#define KS    4
#define PS    6144          // packed projection row stride (q|k|v|g)
#define QO    0
#define KO    1024
#define VO    2048
#define GO    4096

// ---------------------------------------------------------------------------
// Scratch arena (device global — no allocation allowed)
// ---------------------------------------------------------------------------
static constexpr size_t OFF_WPACK = 0;                                  // [1024][6144] tf32-rounded
static constexpr size_t OFF_XR    = OFF_WPACK + (size_t)DD * PS;        // [4096][1024] tf32-rounded x
static constexpr size_t OFF_WOR   = OFF_XR    + (size_t)NTOK * DD;      // [2048][1024] tf32-rounded Wo
static constexpr size_t OFF_WABT  = OFF_WOR   + (size_t)VALD * DD;      // [2][8][1024]
static constexpr size_t OFF_PROJ  = OFF_WABT  + (size_t)2 * HH * DD;    // [4096][6144]
static constexpr size_t OFF_QC    = OFF_PROJ  + (size_t)NTOK * PS;      // [4096][1024]
static constexpr size_t OFF_KC    = OFF_QC    + (size_t)NTOK * KEYD;
static constexpr size_t OFF_VC    = OFF_KC    + (size_t)NTOK * KEYD;    // [4096][2048]
static constexpr size_t OFF_ABCD  = OFF_VC    + (size_t)NTOK * VALD;    // [NTOK*HH][4] = alpha,beta,c,d
static constexpr size_t OFF_OPRE  = OFF_ABCD  + (size_t)NTOK * HH * 4;  // [4096][2048]
static constexpr size_t OFF_YN    = OFF_OPRE  + (size_t)NTOK * VALD;    // [4096][2048] tf32-rounded
static constexpr size_t ARENA_F   = OFF_YN    + (size_t)NTOK * VALD;

__device__ float g_arena[ARENA_F];

// ---------------------------------------------------------------------------
// TF32 helpers
// ---------------------------------------------------------------------------
__device__ __forceinline__ uint32_t f2tf32(float x) {
    uint32_t r;
    asm("cvt.rna.tf32.f32 %0, %1;" : "=r"(r) : "f"(x));
    return r;
}
__device__ __forceinline__ float tf32round(float x) {
    return __uint_as_float(f2tf32(x));
}

__device__ __forceinline__ void mma_tf32(float* c, const uint32_t* a, const uint32_t* b) {
    asm volatile(
        "mma.sync.aligned.m16n8k8.row.col.f32.tf32.tf32.f32 "
        "{%0,%1,%2,%3}, {%4,%5,%6,%7}, {%8,%9}, {%0,%1,%2,%3};"
        : "+f"(c[0]), "+f"(c[1]), "+f"(c[2]), "+f"(c[3])
        : "r"(a[0]), "r"(a[1]), "r"(a[2]), "r"(a[3]), "r"(b[0]), "r"(b[1]));
}

__device__ __forceinline__ void cp16(uint32_t smem_dst, const void* gsrc) {
    asm volatile("cp.async.cg.shared.global [%0], [%1], 16;" :: "r"(smem_dst), "l"(gsrc));
}

// ---------------------------------------------------------------------------
// Packed f32x2 helpers (Blackwell; PTX-only path)
// ---------------------------------------------------------------------------
__device__ __forceinline__ unsigned long long pk2(float lo, float hi) {
    unsigned long long r;
    asm("mov.b64 %0, {%1, %2};" : "=l"(r) : "f"(lo), "f"(hi));
    return r;
}
__device__ __forceinline__ void upk2(float& lo, float& hi, unsigned long long x) {
    asm("mov.b64 {%0, %1}, %2;" : "=f"(lo), "=f"(hi) : "l"(x));
}
__device__ __forceinline__ unsigned long long fma2_(unsigned long long a,
                                                    unsigned long long b,
                                                    unsigned long long c) {
    unsigned long long d;
    asm("fma.rn.f32x2 %0, %1, %2, %3;" : "=l"(d) : "l"(a), "l"(b), "l"(c));
    return d;
}
__device__ __forceinline__ unsigned long long mul2_(unsigned long long a,
                                                    unsigned long long b) {
    unsigned long long d;
    asm("mul.rn.f32x2 %0, %1, %2;" : "=l"(d) : "l"(a), "l"(b));
    return d;
}

// ---------------------------------------------------------------------------
// TF32 tensor-core GEMM on PRE-ROUNDED operands (no cvt in mainloop).
// ---------------------------------------------------------------------------
#define GA_STRIDE 20
#define GB_STRIDE 136

__global__ void __launch_bounds__(256) tf32gemm_kernel(
    const float* __restrict__ A, const float* __restrict__ B,
    float* __restrict__ C, int M, int N, int K)
{
    __shared__ float As[2][128 * GA_STRIDE];
    __shared__ float Bs[2][16 * GB_STRIDE];

    const int tid  = threadIdx.x;
    const int bm   = blockIdx.y, bn = blockIdx.x;
    const int warp = tid >> 5, lane = tid & 31;
    const int wm   = (warp >> 2) * 64;
    const int wn   = (warp & 3) * 32;
    const int gid  = lane >> 2;
    const int tg   = lane & 3;

    const int a_r0 = tid >> 2;
    const int a_c  = (tid & 3) * 4;
    const int b_r0 = tid >> 5;
    const int b_c  = (tid & 31) * 4;

    const float* Ag = A + (size_t)(bm * 128) * K;
    const float* Bg = B + (size_t)bn * 128;

    uint32_t as_base = (uint32_t)__cvta_generic_to_shared(&As[0][0]);
    uint32_t bs_base = (uint32_t)__cvta_generic_to_shared(&Bs[0][0]);
    const uint32_t as_buf = 128 * GA_STRIDE * 4;
    const uint32_t bs_buf = 16 * GB_STRIDE * 4;

    float acc[4][4][4];
#pragma unroll
    for (int i = 0; i < 4; i++)
#pragma unroll
        for (int j = 0; j < 4; j++)
#pragma unroll
            for (int r = 0; r < 4; r++) acc[i][j][r] = 0.f;

    const int niter = K >> 4;

    {
#pragma unroll
        for (int f = 0; f < 2; f++) {
            int row = f * 64 + a_r0;
            cp16(as_base + (uint32_t)((row * GA_STRIDE + a_c) << 2),
                 Ag + (size_t)row * K + a_c);
        }
#pragma unroll
        for (int f = 0; f < 2; f++) {
            int row = f * 8 + b_r0;
            cp16(bs_base + (uint32_t)((row * GB_STRIDE + b_c) << 2),
                 Bg + (size_t)row * N + b_c);
        }
        asm volatile("cp.async.commit_group;");
    }

    for (int it = 0; it < niter; it++) {
        const int p = it & 1;

        if (it + 1 < niter) {
            const int k0 = (it + 1) << 4;
            const uint32_t ao = as_base + (p ^ 1) * as_buf;
            const uint32_t bo = bs_base + (p ^ 1) * bs_buf;
#pragma unroll
            for (int f = 0; f < 2; f++) {
                int row = f * 64 + a_r0;
                cp16(ao + (uint32_t)((row * GA_STRIDE + a_c) << 2),
                     Ag + (size_t)row * K + k0 + a_c);
            }
#pragma unroll
            for (int f = 0; f < 2; f++) {
                int row = f * 8 + b_r0;
                cp16(bo + (uint32_t)((row * GB_STRIDE + b_c) << 2),
                     Bg + (size_t)(k0 + row) * N + b_c);
            }
            asm volatile("cp.async.commit_group;");
            asm volatile("cp.async.wait_group 1;");
        } else {
            asm volatile("cp.async.wait_group 0;");
        }
        __syncthreads();

        const float* Ap = As[p];
        const float* Bp = Bs[p];

#pragma unroll
        for (int ks = 0; ks < 2; ks++) {
            uint32_t af[4][4];
#pragma unroll
            for (int mt = 0; mt < 4; mt++) {
                int r = wm + mt * 16 + gid;
                int c = ks * 8 + tg;
                af[mt][0] = __float_as_uint(Ap[r * GA_STRIDE + c]);
                af[mt][1] = __float_as_uint(Ap[(r + 8) * GA_STRIDE + c]);
                af[mt][2] = __float_as_uint(Ap[r * GA_STRIDE + c + 4]);
                af[mt][3] = __float_as_uint(Ap[(r + 8) * GA_STRIDE + c + 4]);
            }
            uint32_t bf[4][2];
#pragma unroll
            for (int nt = 0; nt < 4; nt++) {
                int n = wn + nt * 8 + gid;
                bf[nt][0] = __float_as_uint(Bp[(ks * 8 + tg) * GB_STRIDE + n]);
                bf[nt][1] = __float_as_uint(Bp[(ks * 8 + 4 + tg) * GB_STRIDE + n]);
            }
#pragma unroll
            for (int mt = 0; mt < 4; mt++)
#pragma unroll
                for (int nt = 0; nt < 4; nt++)
                    mma_tf32(acc[mt][nt], af[mt], bf[nt]);
        }
        __syncthreads();
    }

#pragma unroll
    for (int mt = 0; mt < 4; mt++) {
        int r0 = bm * 128 + wm + mt * 16 + gid;
#pragma unroll
        for (int nt = 0; nt < 4; nt++) {
            int c0 = bn * 128 + wn + nt * 8 + tg * 2;
            *(float2*)(C + (size_t)r0 * N + c0)       = make_float2(acc[mt][nt][0], acc[mt][nt][1]);
            *(float2*)(C + (size_t)(r0 + 8) * N + c0) = make_float2(acc[mt][nt][2], acc[mt][nt][3]);
        }
    }
}

// ---------------------------------------------------------------------------
// Prep kernel (launch 1)
// ---------------------------------------------------------------------------
#define NB_WPACK 24576
#define NB_AB    64
#define NB_XR    16384
#define NB_WOR   8192

__global__ void __launch_bounds__(256) prep_kernel(
    const float* __restrict__ Wq, const float* __restrict__ Wk,
    const float* __restrict__ Wv, const float* __restrict__ Wg,
    const float* __restrict__ Wa, const float* __restrict__ Wb,
    const float* __restrict__ Wo, const float* __restrict__ x,
    float* __restrict__ wpack, float* __restrict__ wabt,
    float* __restrict__ xr, float* __restrict__ wor)
{
    int bid = blockIdx.x;
    if (bid < NB_WPACK) {
        int idx = bid * 256 + threadIdx.x;
        int col = idx % PS, k = idx / PS;
        float v;
        if (col < 1024)      v = Wq[k * 1024 + col];
        else if (col < 2048) v = Wk[k * 1024 + col - 1024];
        else if (col < 4096) v = Wv[k * 2048 + col - 2048];
        else                 v = Wg[k * 2048 + col - 4096];
        wpack[idx] = tf32round(v);
    } else if (bid < NB_WPACK + NB_AB) {
        int idx = (bid - NB_WPACK) * 256 + threadIdx.x;
        int k = idx & 1023, h = (idx >> 10) & 7, a = idx >> 13;
        wabt[idx] = a ? Wb[k * 8 + h] : Wa[k * 8 + h];
    } else if (bid < NB_WPACK + NB_AB + NB_XR) {
        int idx = (bid - NB_WPACK - NB_AB) * 256 + threadIdx.x;
        xr[idx] = tf32round(x[idx]);
    } else {
        int idx = (bid - NB_WPACK - NB_AB - NB_XR) * 256 + threadIdx.x;
        wor[idx] = tf32round(Wo[idx]);
    }
}

// ---------------------------------------------------------------------------
// Fused elementwise kernel (launch 3): ab + conv_q + conv_k + conv_v.
// ---------------------------------------------------------------------------
#define FB_AB   4096
#define FB_CQ   4096
#define FB_CK   4096
#define FB_CV   32768

__device__ __forceinline__ void do_conv_l2(
    const float* __restrict__ in, const float* __restrict__ w,
    float* __restrict__ out, int local_blk)
{
    int gw   = ((local_blk * 256) + (int)threadIdx.x) >> 5;
    int lane = threadIdx.x & 31;
    int h    = gw % HH;
    int bt   = gw / HH;
    int t    = bt % TSEQ;
    int b    = bt / TSEQ;

    int cbase = h * KDIM + lane * 4;

    float acc[4] = {0.f, 0.f, 0.f, 0.f};
    float wt[4][KS];
#pragma unroll
    for (int c = 0; c < 4; c++)
#pragma unroll
        for (int j = 0; j < KS; j++)
            wt[c][j] = w[(cbase + c) * KS + j];

#pragma unroll
    for (int j = 0; j < KS; j++) {
        int tt = t + j - (KS - 1);
        if (tt >= 0) {
            float4 xv = *(const float4*)(in + ((size_t)(b * TSEQ + tt)) * PS + cbase);
#pragma unroll
            for (int c = 0; c < 4; c++)
                acc[c] = fmaf(wt[c][j], (&xv.x)[c], acc[c]);
        }
    }

    float ss = 0.f;
#pragma unroll
    for (int c = 0; c < 4; c++) {
        acc[c] = acc[c] / (1.f + expf(-acc[c]));
        ss = fmaf(acc[c], acc[c], ss);
    }
#pragma unroll
    for (int off = 16; off > 0; off >>= 1)
        ss += __shfl_xor_sync(0xffffffffu, ss, off);
    float s = 1.f / fmaxf(sqrtf(ss), 1e-6f);

    float4 o;
#pragma unroll
    for (int c = 0; c < 4; c++) (&o.x)[c] = acc[c] * s;
    *(float4*)(out + (size_t)bt * KEYD + cbase) = o;
}

__global__ void __launch_bounds__(256) fused_pre_kernel(
    const float* __restrict__ x, const float* __restrict__ proj,
    const float* __restrict__ wabt,
    const float* __restrict__ A_log, const float* __restrict__ dt_bias,
    const float* __restrict__ conv_q, const float* __restrict__ conv_k,
    const float* __restrict__ conv_v,
    float* __restrict__ abcd,
    float* __restrict__ qc, float* __restrict__ kc, float* __restrict__ vc)
{
    __shared__ float xs[DD];
    int bid = blockIdx.x;

    if (bid < FB_AB) {
        int t = bid;
        for (int i = threadIdx.x; i < DD; i += 256)
            xs[i] = x[(size_t)t * DD + i];
        __syncthreads();

        int warp = threadIdx.x >> 5;
        int lane = threadIdx.x & 31;
        const float* wa = wabt + warp * 1024;
        const float* wb = wabt + 8192 + warp * 1024;

        float sa = 0.f, sb = 0.f;
#pragma unroll 4
        for (int kk = lane; kk < DD; kk += 32) {
            float xv = xs[kk];
            sa = fmaf(xv, wa[kk], sa);
            sb = fmaf(xv, wb[kk], sb);
        }
#pragma unroll
        for (int off = 16; off > 0; off >>= 1) {
            sa += __shfl_xor_sync(0xffffffffu, sa, off);
            sb += __shfl_xor_sync(0xffffffffu, sb, off);
        }
        if (lane == 0) {
            float z  = sa + dt_bias[warp];
            float sp = (z > 20.f) ? z : log1pf(expf(z));
            float alpha = expf(-expf(A_log[warp]) * sp);
            float beta  = 2.f / (1.f + expf(-sb));
            *(float2*)(abcd + (size_t)(t * HH + warp) * 4) = make_float2(alpha, beta);
        }
    } else if (bid < FB_AB + FB_CQ) {
        do_conv_l2(proj + QO, conv_q, qc, bid - FB_AB);
    } else if (bid < FB_AB + FB_CQ + FB_CK) {
        do_conv_l2(proj + KO, conv_k, kc, bid - FB_AB - FB_CQ);
    } else {
        int idx = (bid - FB_AB - FB_CQ - FB_CK) * 256 + threadIdx.x;
        int c  = idx % VALD;
        int bt = idx / VALD;
        int t  = bt % TSEQ;
        int b  = bt / TSEQ;

        float acc = 0.f;
#pragma unroll
        for (int j = 0; j < KS; j++) {
            int tt = t + j - (KS - 1);
            if (tt >= 0)
                acc = fmaf(conv_v[c * KS + j],
                           proj[VO + ((size_t)(b * TSEQ + tt)) * PS + c], acc);
        }
        vc[idx] = acc / (1.f + expf(-acc));
    }
}

// ---------------------------------------------------------------------------
// ckd kernel (launch 4): c_t = k_t.k_{t+1} (0 at seq end), d_t = k_t.q_t
// ---------------------------------------------------------------------------
__global__ void __launch_bounds__(256) ckd_kernel(
    const float* __restrict__ qc, const float* __restrict__ kc,
    float* __restrict__ abcd)
{
    int gw   = (blockIdx.x * 256 + threadIdx.x) >> 5;   // bt*HH + h
    int lane = threadIdx.x & 31;
    int h    = gw & 7;
    int bt   = gw >> 3;
    int t    = bt & (TSEQ - 1);

    const float* kp = kc + (size_t)bt * KEYD + h * KDIM + lane * 4;
    const float* qp = qc + (size_t)bt * KEYD + h * KDIM + lane * 4;
    float4 kt = *(const float4*)kp;
    float4 qt = *(const float4*)qp;
    float4 kn = make_float4(0.f, 0.f, 0.f, 0.f);
    if (t < TSEQ - 1) kn = *(const float4*)(kp + KEYD);

    float c = kt.x * kn.x + kt.y * kn.y + kt.z * kn.z + kt.w * kn.w;
    float d = kt.x * qt.x + kt.y * qt.y + kt.z * qt.z + kt.w * qt.w;
#pragma unroll
    for (int off = 16; off > 0; off >>= 1) {
        c += __shfl_xor_sync(0xffffffffu, c, off);
        d += __shfl_xor_sync(0xffffffffu, d, off);
    }
    if (lane == 0)
        *(float2*)(abcd + (size_t)gw * 4 + 2) = make_float2(c, d);
}

// ---------------------------------------------------------------------------
// Recurrent delta-rule scan (launch 5): lookahead-1 algebra + packed f32x2
// state + cp.async double-buffered smem staging (CH=16 timesteps/chunk).
//
// smem k/q row layout: 8 chunks of 16 floats at 20-word stride (80 B) —
// ksub word offsets {0,20,8,28,16,4,24,12} mod 32: conflict-free b64 reads,
// 16B-aligned cp.async destinations.
// ---------------------------------------------------------------------------
#define CH     16
#define NCH    (TSEQ / CH)     // 128
#define ROW_W  160             // words per padded k/q row (8 * 20)
#define ROW_B  (ROW_W * 4)     // 640 bytes

__global__ void __launch_bounds__(256) scan_kernel(
    const float* __restrict__ q, const float* __restrict__ k,
    const float* __restrict__ v, const float* __restrict__ abcd,
    float* __restrict__ o)
{
    __shared__ __align__(16) float sk [2][(CH + 1) * ROW_W];
    __shared__ __align__(16) float sq [2][CH * ROW_W];
    __shared__ __align__(16) float sv [2][CH * 32];
    __shared__ __align__(16) float ssc[2][CH * 4];

    int bid  = blockIdx.x;
    int vblk = bid & 7;
    int h    = (bid >> 3) & 7;
    int b    = bid >> 6;

    int tid   = threadIdx.x;
    int warp  = tid >> 5;
    int lane  = tid & 31;
    int rowid = lane & 3;
    int ksub  = lane >> 2;
    int vloc  = warp * 4 + rowid;           // 0..31

    const float* kg = k + (size_t)(b * TSEQ) * KEYD + h * KDIM;
    const float* qg = q + (size_t)(b * TSEQ) * KEYD + h * KDIM;
    const float* vg = v + (size_t)(b * TSEQ) * VALD + h * VDIM + vblk * 32;
    const float* sg = abcd + (size_t)(b * TSEQ) * (HH * 4) + h * 4;
    float*       og = o + (size_t)(b * TSEQ) * VALD + h * VDIM + vblk * 32 + vloc;

    uint32_t skb  = (uint32_t)__cvta_generic_to_shared(&sk[0][0]);
    uint32_t sqb  = (uint32_t)__cvta_generic_to_shared(&sq[0][0]);
    uint32_t svb  = (uint32_t)__cvta_generic_to_shared(&sv[0][0]);
    uint32_t sscb = (uint32_t)__cvta_generic_to_shared(&ssc[0][0]);
    const uint32_t SKBUF  = (CH + 1) * ROW_B;
    const uint32_t SQBUF  = CH * ROW_B;
    const uint32_t SVBUF  = CH * 32 * 4;
    const uint32_t SSCBUF = CH * 16;

    // issue cp.async loads for chunk starting at time `base` into buffer `p`
#define ISSUE_CHUNK(p, base)                                                   \
    {                                                                          \
        uint32_t kb = skb + (uint32_t)(p) * SKBUF;                             \
        _Pragma("unroll")                                                      \
        for (int pass = 0; pass < 3; pass++) {                                 \
            int f = tid + pass * 256;                                          \
            if (f < (CH + 1) * 32) {                                           \
                int row = f >> 5, m = f & 31;                                  \
                int t = (base) + row; t = t < TSEQ ? t : TSEQ - 1;             \
                cp16(kb + (uint32_t)(row * ROW_B + (m >> 2) * 80 + (m & 3) * 16), \
                     kg + (size_t)t * KEYD + m * 4);                           \
            }                                                                  \
        }                                                                      \
        uint32_t qb = sqb + (uint32_t)(p) * SQBUF;                             \
        _Pragma("unroll")                                                      \
        for (int pass = 0; pass < 2; pass++) {                                 \
            int f = tid + pass * 256;                                          \
            int row = f >> 5, m = f & 31;                                      \
            cp16(qb + (uint32_t)(row * ROW_B + (m >> 2) * 80 + (m & 3) * 16),  \
                 qg + (size_t)((base) + row) * KEYD + m * 4);                  \
        }                                                                      \
        if (tid < 128) {                                                       \
            int row = tid >> 3, j = tid & 7;                                   \
            cp16(svb + (uint32_t)(p) * SVBUF + (uint32_t)((row * 32 + j * 4) * 4), \
                 vg + (size_t)((base) + row) * VALD + j * 4);                  \
        }                                                                      \
        if (tid < CH) {                                                        \
            cp16(sscb + (uint32_t)(p) * SSCBUF + (uint32_t)(tid * 16),         \
                 sg + (size_t)((base) + tid) * (HH * 4));                      \
        }                                                                      \
        asm volatile("cp.async.commit_group;");                                \
    }

    unsigned long long S2[8];
#pragma unroll
    for (int i = 0; i < 8; i++) S2[i] = 0ull;
    float u = 0.f, pa = 0.f, pcoef = 0.f, pcc = 0.f;

    ISSUE_CHUNK(0, 0);

    for (int c = 0; c < NCH; c++) {
        int p = c & 1;
        if (c + 1 < NCH) {
            ISSUE_CHUNK(p ^ 1, (c + 1) * CH);
            asm volatile("cp.async.wait_group 1;");
        } else {
            asm volatile("cp.async.wait_group 0;");
        }
        __syncthreads();

        const char* skp = (const char*)&sk[p][0];
        const char* sqp = (const char*)&sq[p][0];
        const float* svp = &sv[p][0];
        const float* sscp = &ssc[p][0];
        int base = c * CH;

#pragma unroll 4
        for (int tl = 0; tl < CH; tl++) {
            float4 sc = *(const float4*)(sscp + tl * 4);
            float aa = sc.x, bv = sc.y, cc = sc.z, dd = sc.w;
            float vv = svp[tl * 32 + vloc];

            float r    = fmaf(pa, u, pcoef * pcc);
            float coef = fmaf(-(aa * bv), r, bv * vv);

            const char* krow = skp + tl * ROW_B + ksub * 80;
            const char* qrow = sqp + tl * ROW_B + ksub * 80;

            unsigned long long ua = 0ull, wa = 0ull;
#pragma unroll
            for (int i = 0; i < 8; i++) {
                unsigned long long kn = *(const unsigned long long*)(krow + ROW_B + i * 8);
                unsigned long long qq = *(const unsigned long long*)(qrow + i * 8);
                ua = fma2_(S2[i], kn, ua);
                wa = fma2_(S2[i], qq, wa);
            }
            float ul, uh, wl, wh;
            upk2(ul, uh, ua);
            upk2(wl, wh, wa);
            float un = ul + uh, wn = wl + wh;
            un += __shfl_xor_sync(0xffffffffu, un, 4);
            un += __shfl_xor_sync(0xffffffffu, un, 8);
            un += __shfl_xor_sync(0xffffffffu, un, 16);
            wn += __shfl_xor_sync(0xffffffffu, wn, 4);
            wn += __shfl_xor_sync(0xffffffffu, wn, 8);
            wn += __shfl_xor_sync(0xffffffffu, wn, 16);

            unsigned long long aa2 = pk2(aa, aa);
            unsigned long long cf2 = pk2(coef, coef);
#pragma unroll
            for (int i = 0; i < 8; i++) {
                unsigned long long kt = *(const unsigned long long*)(krow + i * 8);
                S2[i] = fma2_(kt, cf2, mul2_(aa2, S2[i]));
            }

            float ov = fmaf(coef, dd, aa * wn);
            if (ksub == 0) og[(size_t)(base + tl) * VALD] = ov;

            u = un; pa = aa; pcoef = coef; pcc = cc;
        }
        __syncthreads();
    }
#undef ISSUE_CHUNK
}

// ---------------------------------------------------------------------------
// RMS norm + weight + SiLU(gate), tf32-rounded output. One warp per (bt,h).
// ---------------------------------------------------------------------------
__global__ void __launch_bounds__(256) normgate_kernel(
    const float* __restrict__ o, const float* __restrict__ proj,
    const float* __restrict__ w, float* __restrict__ y)
{
    int gw   = (blockIdx.x * 256 + threadIdx.x) >> 5;   // bt*H + h
    int lane = threadIdx.x & 31;
    int bt   = gw >> 3, h = gw & 7;

    const float* op = o + (size_t)gw * VDIM + lane * 8;
    const float* gp = proj + GO + (size_t)bt * PS + h * VDIM + lane * 8;
    float*       yp = y + (size_t)gw * VDIM + lane * 8;

    float vals[8];
    *(float4*)(vals)     = *(const float4*)(op);
    *(float4*)(vals + 4) = *(const float4*)(op + 4);

    float ss = 0.f;
#pragma unroll
    for (int i = 0; i < 8; i++) ss = fmaf(vals[i], vals[i], ss);
#pragma unroll
    for (int off = 16; off > 0; off >>= 1)
        ss += __shfl_xor_sync(0xffffffffu, ss, off);
    float rms = rsqrtf(ss * (1.f / VDIM) + 1e-5f);

    float gv[8];
    *(float4*)(gv)     = *(const float4*)(gp);
    *(float4*)(gv + 4) = *(const float4*)(gp + 4);

    float out[8];
#pragma unroll
    for (int i = 0; i < 8; i++) {
        float gg   = gv[i];
        float silu = gg / (1.f + expf(-gg));
        out[i] = tf32round(vals[i] * rms * w[lane * 8 + i] * silu);
    }
    *(float4*)(yp)     = *(float4*)(out);
    *(float4*)(yp + 4) = *(float4*)(out + 4);
}

// ---------------------------------------------------------------------------
// Host launcher
// ---------------------------------------------------------------------------
extern "C" void kernel_launch(void* const* d_in, const int* in_sizes, int n_in,
                              void* d_out, int out_size)
{
    const float* x       = (const float*)d_in[0];
    const float* Wq      = (const float*)d_in[1];
    const float* Wk      = (const float*)d_in[2];
    const float* Wv      = (const float*)d_in[3];
    const float* Wa      = (const float*)d_in[4];
    const float* Wb      = (const float*)d_in[5];
    const float* Wg      = (const float*)d_in[6];
    const float* Wo      = (const float*)d_in[7];
    const float* A_log   = (const float*)d_in[8];
    const float* dt_bias = (const float*)d_in[9];
    const float* conv_q  = (const float*)d_in[10];
    const float* conv_k  = (const float*)d_in[11];
    const float* conv_v  = (const float*)d_in[12];
    const float* o_w     = (const float*)d_in[13];
    float* out = (float*)d_out;

    float* arena = nullptr;
    cudaGetSymbolAddress((void**)&arena, g_arena);

    float* wpack = arena + OFF_WPACK;
    float* xr    = arena + OFF_XR;
    float* wor   = arena + OFF_WOR;
    float* wabt  = arena + OFF_WABT;
    float* proj  = arena + OFF_PROJ;
    float* qc    = arena + OFF_QC;
    float* kc    = arena + OFF_KC;
    float* vc    = arena + OFF_VC;
    float* abcd  = arena + OFF_ABCD;
    float* opre  = arena + OFF_OPRE;
    float* yn    = arena + OFF_YN;

    dim3 blk(256);

    // 1. pack + tf32-round all GEMM operands
    prep_kernel<<<NB_WPACK + NB_AB + NB_XR + NB_WOR, blk>>>(
        Wq, Wk, Wv, Wg, Wa, Wb, Wo, x, wpack, wabt, xr, wor);

    // 2. fused q|k|v|g projection (pre-rounded TF32)
    tf32gemm_kernel<<<dim3(PS / 128, NTOK / 128), blk>>>(xr, wpack, proj, NTOK, PS, DD);

    // 3. fused alpha/beta + convs
    fused_pre_kernel<<<FB_AB + FB_CQ + FB_CK + FB_CV, blk>>>(
        x, proj, wabt, A_log, dt_bias, conv_q, conv_k, conv_v,
        abcd, qc, kc, vc);

    // 4. precompute c = k_t.k_{t+1}, d = k_t.q_t
    ckd_kernel<<<(NTOK * HH) / 8, blk>>>(qc, kc, abcd);

    // 5. recurrent scan (lookahead-1, packed f32x2, smem-staged)
    scan_kernel<<<BB * HH * (VDIM / 32), blk>>>(qc, kc, vc, abcd, opre);

    // 6. rms norm + gate (tf32-rounded output)
    normgate_kernel<<<(NTOK * HH) / 8, blk>>>(opre, proj, o_w, yn);

    // 7. output projection (pre-rounded TF32)
    tf32gemm_kernel<<<dim3(DD / 128, NTOK / 128), blk>>>(yn, wor, out, NTOK, DD, VALD);
}